// round 11
// baseline (speedup 1.0000x reference)
#include <cuda_runtime.h>
#include <cuda_fp16.h>
#include <cstdint>
#include <math.h>

#define B_    64
#define T_    1024
#define D_    512
#define KTAP  5
#define U_    256
#define G4_   1024
#define TP_   (T_ + 4)
#define XPD_  (TP_ * D_)
#define RNN_CTAS 64

#define BM    128
#define BN    128
#define KC    32                 // fp16 k per chunk
#define ROWB  80                 // smem row stride (bytes) -> conflict-free ldmatrix
#define TILEB (128 * ROWB)       // 10240 B per tile
#define STAGEB (3 * TILEB)       // A, BH, BL
#define NSTG  3
#define GSMEM (NSTG * STAGEB)    // 90 KB -> 2 CTAs/SM

// ---------------- scratch ----------------
__device__ uint16_t g_x0[(size_t)B_ * XPD_];        // fp16 activation planes
__device__ uint16_t g_x1[(size_t)B_ * XPD_];
__device__ uint16_t g_wch[(size_t)3 * 512 * 2560];  // conv weights hi [i][n][kk]
__device__ uint16_t g_wcl[(size_t)3 * 512 * 2560];  // conv weights lo
__device__ uint16_t g_wlh[(size_t)2 * 1024 * 512];  // lstm kernels hi [dir][n][d]
__device__ uint16_t g_wll[(size_t)2 * 1024 * 512];  // lstm kernels lo
__device__ float    g_pre_f[(size_t)T_ * B_ * G4_];
__device__ float    g_pre_b[(size_t)T_ * B_ * G4_];
__device__ float    g_h[2][2][B_ * U_];
__device__ unsigned g_flags[2][64 * 32];            // per-CTA step flags, 128B apart
__device__ unsigned g_epoch[2][32];                 // per-dir epoch word

// ---------------- helpers ----------------
__device__ __forceinline__ uint32_t smem_u32(const void* p) {
    uint32_t a;
    asm("{ .reg .u64 t; cvta.to.shared.u64 t, %1; cvt.u32.u64 %0, t; }" : "=r"(a) : "l"(p));
    return a;
}
__device__ __forceinline__ uint16_t f2h(float v) {
    return __half_as_ushort(__float2half(v));
}
__device__ __forceinline__ void split_h16(float v, uint16_t& h, uint16_t& l) {
    __half hh = __float2half(v);
    float hf = __half2float(hh);
    h = __half_as_ushort(hh);
    l = __half_as_ushort(__float2half(v - hf));
}
#define CP16(dst, src) \
    asm volatile("cp.async.cg.shared.global [%0], [%1], 16;" :: "r"(dst), "l"(src))
#define CP_COMMIT() asm volatile("cp.async.commit_group;" ::: "memory")
#define CP_WAIT(N)  asm volatile("cp.async.wait_group %0;" :: "n"(N) : "memory")
#define LDM_X4(R0, R1, R2, R3, ADDR)                                            \
    asm volatile("ldmatrix.sync.aligned.m8n8.x4.shared.b16 {%0,%1,%2,%3}, [%4];"\
        : "=r"(R0), "=r"(R1), "=r"(R2), "=r"(R3) : "r"(ADDR))
__device__ __forceinline__ void mma_f16(float* c, const uint32_t* a, const uint32_t* b) {
    asm volatile(
        "mma.sync.aligned.m16n8k16.row.col.f32.f16.f16.f32 "
        "{%0,%1,%2,%3}, {%4,%5,%6,%7}, {%8,%9}, {%0,%1,%2,%3};"
        : "+f"(c[0]), "+f"(c[1]), "+f"(c[2]), "+f"(c[3])
        : "r"(a[0]), "r"(a[1]), "r"(a[2]), "r"(a[3]), "r"(b[0]), "r"(b[1]));
}
// packed fp32x2 (Blackwell)
#define PACK2(d, lo, hi) asm("mov.b64 %0, {%1, %2};" : "=l"(d) : "f"(lo), "f"(hi))
#define UNPACK2(lo, hi, s) asm("mov.b64 {%0, %1}, %2;" : "=f"(lo), "=f"(hi) : "l"(s))
#define FMA2(d, a, b) asm("fma.rn.f32x2 %0, %1, %2, %0;" : "+l"(d) : "l"(a), "l"(b))

// ---------------- init ----------------
__global__ void init_kernel() {
    int idx = blockIdx.x * blockDim.x + threadIdx.x;
    int nh = B_ * 4 * D_;
    if (idx < nh) {
        int b = idx / (4 * D_);
        int r = (idx / D_) & 3;
        int d = idx % D_;
        int row = (r < 2) ? r : (TP_ - 4 + r);
        size_t o = (size_t)b * XPD_ + (size_t)row * D_ + d;
        g_x0[o] = 0; g_x1[o] = 0;
    }
    if (idx < 2 * 2 * B_ * U_) ((float*)g_h)[idx] = 0.f;
    if (idx < 2 * 64 * 32) ((unsigned*)g_flags)[idx] = 0u;
    if (idx < 2 * 32) ((unsigned*)g_epoch)[idx] = 0u;
}

// ---------------- pack input (single fp16) ----------------
__global__ void pad_pack(const float* __restrict__ in) {
    size_t total = (size_t)B_ * T_ * D_;
    for (size_t idx = (size_t)blockIdx.x * blockDim.x + threadIdx.x;
         idx < total; idx += (size_t)gridDim.x * blockDim.x) {
        size_t b = idx / ((size_t)T_ * D_);
        size_t r = idx % ((size_t)T_ * D_);
        size_t t = r / D_, d = r % D_;
        g_x0[b * XPD_ + (t + 2) * D_ + d] = f2h(in[idx]);
    }
}

// ---------------- transpose + split weights (fp16 hi/lo) ----------------
__global__ void wprep(const float* __restrict__ convk,
                      const float* __restrict__ wkf, const float* __restrict__ wkb) {
    const size_t CONVN = (size_t)3 * 512 * 2560;
    const size_t LSTMN = (size_t)1024 * 512;
    size_t total = CONVN + 2 * LSTMN;
    for (size_t idx = (size_t)blockIdx.x * blockDim.x + threadIdx.x;
         idx < total; idx += (size_t)gridDim.x * blockDim.x) {
        uint16_t h, l;
        if (idx < CONVN) {
            size_t i = idx / ((size_t)512 * 2560);
            size_t r = idx % ((size_t)512 * 2560);
            size_t n = r / 2560, kk = r % 2560;
            size_t tap = kk >> 9, din = kk & 511;
            split_h16(convk[(((i * KTAP + tap) * D_) + din) * D_ + n], h, l);
            g_wch[idx] = h; g_wcl[idx] = l;
        } else if (idx < CONVN + LSTMN) {
            size_t j = idx - CONVN;
            size_t n = j >> 9, d = j & 511;
            split_h16(wkf[d * G4_ + n], h, l);
            g_wlh[j] = h; g_wll[j] = l;
        } else {
            size_t j = idx - CONVN - LSTMN;
            size_t n = j >> 9, d = j & 511;
            split_h16(wkb[d * G4_ + n], h, l);
            g_wlh[LSTMN + j] = h; g_wll[LSTMN + j] = l;
        }
    }
}

// ---------------- fp16 2-term warp-MMA GEMM (A single, B split hi/lo) ----------------
template <int MODE>
__global__ __launch_bounds__(256, 2) void mma_gemm(
    const uint16_t* __restrict__ Ap,
    const uint16_t* __restrict__ Bh, const uint16_t* __restrict__ Bl,
    int KKtot,
    const float* __restrict__ bias,
    const float* __restrict__ bng, const float* __restrict__ bnb,
    const float* __restrict__ bnm, const float* __restrict__ bnv,
    uint16_t* __restrict__ Cp, float* __restrict__ Cf)
{
    extern __shared__ char smraw[];
    const uint32_t sbase = smem_u32(smraw);

    const int tid = threadIdx.x;
    const int wid = tid >> 5, lane = tid & 31;
    const int bz = blockIdx.z;
    const int t0 = blockIdx.y * BM;
    const int n0 = blockIdx.x * BN;
    const int wm = wid & 1;
    const int wn = wid >> 1;

    const uint32_t a_off = (uint32_t)((wm * 64 + (lane & 15)) * ROWB + (lane >> 4) * 16);
    const uint32_t b_off = (uint32_t)((wn * 32 + (lane & 7) + ((lane >> 4) << 3)) * ROWB
                                      + ((lane >> 3) & 1) * 16);

    const uint16_t* Ab = Ap + (size_t)bz * XPD_;
    const int NCH = KKtot / KC;

    float cacc[4][4][4];
#pragma unroll
    for (int i = 0; i < 4; i++)
#pragma unroll
        for (int j = 0; j < 4; j++)
#pragma unroll
            for (int q = 0; q < 4; q++) cacc[i][j][q] = 0.f;

    auto issue = [&](int cc) {
        const int st = cc % NSTG;
        const int kk0 = cc * KC;
        const int tap = kk0 >> 9;
        const int d0 = kk0 & 511;
        const uint32_t sb = sbase + st * STAGEB;
#pragma unroll
        for (int half = 0; half < 2; half++) {
            const int s = tid + half * 256;
            const int row = s >> 2, seg = s & 3;
            const uint32_t doff = (uint32_t)(row * ROWB + seg * 16);
            const size_t aoff = (size_t)(t0 + row + tap) * D_ + d0 + seg * 8;
            const size_t boff = (size_t)(n0 + row) * KKtot + kk0 + seg * 8;
            CP16(sb + doff,             Ab + aoff);
            CP16(sb + TILEB + doff,     Bh + boff);
            CP16(sb + 2 * TILEB + doff, Bl + boff);
        }
        CP_COMMIT();
    };

    auto compute = [&](int st) {
        const uint32_t SB = sbase + st * STAGEB;
#pragma unroll
        for (int k16 = 0; k16 < 2; k16++) {
            const uint32_t kof = k16 * 32;
            uint32_t bh[4][2], bl[4][2];
#pragma unroll
            for (int nfp = 0; nfp < 2; nfp++) {
                uint32_t bd = SB + TILEB + b_off + nfp * (16 * ROWB) + kof;
                LDM_X4(bh[2 * nfp][0], bh[2 * nfp][1], bh[2 * nfp + 1][0], bh[2 * nfp + 1][1], bd);
                LDM_X4(bl[2 * nfp][0], bl[2 * nfp][1], bl[2 * nfp + 1][0], bl[2 * nfp + 1][1], bd + TILEB);
            }
#pragma unroll
            for (int mf = 0; mf < 4; mf++) {
                uint32_t af[4];
                uint32_t ad = SB + a_off + mf * (16 * ROWB) + kof;
                LDM_X4(af[0], af[1], af[2], af[3], ad);
#pragma unroll
                for (int nf = 0; nf < 4; nf++) {
                    mma_f16(cacc[mf][nf], af, bh[nf]);
                    mma_f16(cacc[mf][nf], af, bl[nf]);
                }
            }
        }
    };

    issue(0);
    issue(1);

    for (int cc = 0; cc < NCH; cc++) {
        CP_WAIT(1);
        __syncthreads();
        if (cc + 2 < NCH) issue(cc + 2);
        else CP_COMMIT();
        compute(cc % NSTG);
    }

    // ---------------- epilogue ----------------
    const int r0 = lane >> 2;
    const int cq = (lane & 3) * 2;
    float mul0[4], mul1[4], add0[4], add1[4];
#pragma unroll
    for (int nf = 0; nf < 4; nf++) {
        int n = n0 + wn * 32 + nf * 8 + cq;
        float b0 = __ldg(&bias[n]), b1 = __ldg(&bias[n + 1]);
        if (MODE == 0) {
            float s0 = __ldg(&bng[n]) * rsqrtf(__ldg(&bnv[n]) + 1e-3f);
            float s1 = __ldg(&bng[n + 1]) * rsqrtf(__ldg(&bnv[n + 1]) + 1e-3f);
            mul0[nf] = s0; mul1[nf] = s1;
            add0[nf] = s0 * (b0 - __ldg(&bnm[n])) + __ldg(&bnb[n]);
            add1[nf] = s1 * (b1 - __ldg(&bnm[n + 1])) + __ldg(&bnb[n + 1]);
        } else {
            mul0[nf] = 1.f; mul1[nf] = 1.f;
            add0[nf] = b0;  add1[nf] = b1;
        }
    }

#pragma unroll
    for (int mf = 0; mf < 4; mf++) {
#pragma unroll
        for (int half = 0; half < 2; half++) {
            int m = wm * 64 + mf * 16 + r0 + half * 8;
#pragma unroll
            for (int nf = 0; nf < 4; nf++) {
                float v0 = fmaf(cacc[mf][nf][2 * half + 0], mul0[nf], add0[nf]);
                float v1 = fmaf(cacc[mf][nf][2 * half + 1], mul1[nf], add1[nf]);
                int nc = n0 + wn * 32 + nf * 8 + cq;
                if (MODE == 0) {
                    v0 = fmaxf(v0, 0.f);
                    v1 = fmaxf(v1, 0.f);
                    size_t off = (size_t)bz * XPD_ + (size_t)(t0 + m + 2) * D_ + nc;
                    *(uint32_t*)(Cp + off) = (uint32_t)f2h(v0) | ((uint32_t)f2h(v1) << 16);
                } else {
                    int t = t0 + m;
                    size_t off = (MODE == 1)
                        ? ((size_t)t * B_ + bz) * G4_ + nc
                        : ((size_t)(T_ - 1 - t) * B_ + bz) * G4_ + nc;
                    *(float2*)(Cf + off) = make_float2(v0, v1);
                }
            }
        }
    }
}

// ---------------- persistent bi-LSTM recurrence (R8 compute form) ----------------
// Changes vs R8: hierarchical epoch barrier (128B-spaced flags, aggregator CTA,
// single epoch poll) and out-store deferred past the flag release.
__global__ __launch_bounds__(256) void lstm_kernel(
    const float* __restrict__ pre_f, const float* __restrict__ pre_b,
    const float* __restrict__ wr_f,  const float* __restrict__ wr_b,
    float* __restrict__ out)
{
    extern __shared__ float sm[];
    float* sW = sm;            // [128][4][4][2] = 4096 floats
    float* sH = sm + 4096;     // [64][260]

    const int bx  = blockIdx.x;
    const int dir = bx >> 6;
    const int cta = bx & 63;
    const int u0  = cta << 2;
    const float* pre = dir ? pre_b : pre_f;
    const float* Wr  = dir ? wr_b  : wr_f;
    unsigned* flags = &g_flags[dir][0];
    unsigned* epoch = &g_epoch[dir][0];

    const int tid = threadIdx.x;
    const int wid = tid >> 5, lane = tid & 31;
    const int b = tid >> 2, q = tid & 3, u = u0 + q;

    // paired weight layout: idx = k2*32 + qq*8 + g*2 + par, k = 2*k2 + par
    for (int idx = tid; idx < 4096; idx += 256) {
        int par = idx & 1;
        int rest = idx >> 1;
        int g = rest & 3, qq = (rest >> 2) & 3, k2 = rest >> 4;
        int k = 2 * k2 + par;
        sW[idx] = Wr[(size_t)k * G4_ + g * U_ + u0 + qq];
    }

    float c = 0.f;
    float* h0 = &g_h[dir][0][0];
    float* h1 = &g_h[dir][1][0];
    __syncthreads();

    const uint64_t* wbase = (const uint64_t*)(sW) + q * 4;

    for (int t = 0; t < T_; t++) {
        // prefetch pre-activations
        const float* p = pre + ((size_t)t * B_ + b) * G4_ + u;
        float z0 = __ldg(&p[0]);
        float z1 = __ldg(&p[U_]);
        float z2 = __ldg(&p[2 * U_]);
        float z3 = __ldg(&p[3 * U_]);

        // cooperative staging (16 independent ldcg float4 per thread)
        const float* hr = ((t + 1) & 1) ? h1 : h0;
        for (int idx = tid * 4; idx < B_ * U_; idx += 1024) {
            float4 v = __ldcg((const float4*)(hr + idx));
            int row = idx >> 8, col = idx & 255;
            *(float4*)&sH[row * 260 + col] = v;
        }
        __syncthreads();

        uint64_t ai, af, ag, ao;
        PACK2(ai, z0, 0.f);
        PACK2(af, z1, 0.f);
        PACK2(ag, z2, 0.f);
        PACK2(ao, z3, 0.f);

        const float* hrow = &sH[b * 260];
#pragma unroll 8
        for (int k2 = 0; k2 < U_ / 2; k2++) {
            uint64_t h2 = *(const uint64_t*)(hrow + k2 * 2);
            const uint64_t* wp = wbase + k2 * 16;
            FMA2(ai, h2, wp[0]);
            FMA2(af, h2, wp[1]);
            FMA2(ag, h2, wp[2]);
            FMA2(ao, h2, wp[3]);
        }
        float e0, e1;
        UNPACK2(e0, e1, ai); z0 = e0 + e1;
        UNPACK2(e0, e1, af); z1 = e0 + e1;
        UNPACK2(e0, e1, ag); z2 = e0 + e1;
        UNPACK2(e0, e1, ao); z3 = e0 + e1;

        float ig = 1.f / (1.f + __expf(-z0));
        float fg = 1.f / (1.f + __expf(-z1));
        float gg = tanhf(z2);
        float og = 1.f / (1.f + __expf(-z3));
        c = fg * c + ig * gg;
        float h = og * tanhf(c);

        // h store first (the only data other CTAs need)
        float* hw = (t & 1) ? h1 : h0;
        hw[b * U_ + u] = h;

        __syncthreads();                 // all h writes of this CTA issued
        const unsigned tgt = (unsigned)(t + 1);
        if (tid == 0) {
            __threadfence();             // drain h stores to gpu scope
            asm volatile("st.global.release.gpu.u32 [%0], %1;"
                         :: "l"(flags + cta * 32), "r"(tgt) : "memory");
        }

        // deferred out store: overlaps the barrier wait, not fenced
        int tout = dir ? (T_ - 1 - t) : t;
        out[((size_t)b * T_ + tout) * (2 * U_) + dir * U_ + u] = h;

        // aggregator (cta 0 of each dir): poll all 64 flags, then release epoch
        if (cta == 0 && wid == 0) {
            unsigned v0, v1;
            do {
                asm volatile("ld.global.acquire.gpu.u32 %0, [%1];"
                             : "=r"(v0) : "l"(flags + lane * 32));
                asm volatile("ld.global.acquire.gpu.u32 %0, [%1];"
                             : "=r"(v1) : "l"(flags + (lane + 32) * 32));
            } while (__any_sync(0xFFFFFFFFu, (v0 < tgt) | (v1 < tgt)));
            if (lane == 0) {
                asm volatile("st.global.release.gpu.u32 [%0], %1;"
                             :: "l"(epoch), "r"(tgt) : "memory");
            }
        }
        // everyone else: poll the single epoch word
        if (cta != 0 && tid == 0) {
            unsigned v;
            do {
                asm volatile("ld.global.acquire.gpu.u32 %0, [%1];"
                             : "=r"(v) : "l"(epoch));
            } while (v < tgt);
        }
        __syncthreads();
    }
}

// ---------------- launcher ----------------
extern "C" void kernel_launch(void* const* d_in, const int* in_sizes, int n_in,
                              void* d_out, int out_size)
{
    const float* inputs = (const float*)d_in[0];
    const float* convk  = (const float*)d_in[1];
    const float* convb  = (const float*)d_in[2];
    const float* bng    = (const float*)d_in[3];
    const float* bnb    = (const float*)d_in[4];
    const float* bnm    = (const float*)d_in[5];
    const float* bnv    = (const float*)d_in[6];
    const float* wk_f   = (const float*)d_in[7];
    const float* wr_f   = (const float*)d_in[8];
    const float* bi_f   = (const float*)d_in[9];
    const float* wk_b   = (const float*)d_in[10];
    const float* wr_b   = (const float*)d_in[11];
    const float* bi_b   = (const float*)d_in[12];
    float* out = (float*)d_out;

    uint16_t *x0, *x1, *wch, *wcl, *wlh, *wll;
    float *pre_f, *pre_b;
    cudaGetSymbolAddress((void**)&x0, g_x0);
    cudaGetSymbolAddress((void**)&x1, g_x1);
    cudaGetSymbolAddress((void**)&wch, g_wch);
    cudaGetSymbolAddress((void**)&wcl, g_wcl);
    cudaGetSymbolAddress((void**)&wlh, g_wlh);
    cudaGetSymbolAddress((void**)&wll, g_wll);
    cudaGetSymbolAddress((void**)&pre_f, g_pre_f);
    cudaGetSymbolAddress((void**)&pre_b, g_pre_b);

    cudaFuncSetAttribute(mma_gemm<0>, cudaFuncAttributeMaxDynamicSharedMemorySize, GSMEM);
    cudaFuncSetAttribute(mma_gemm<1>, cudaFuncAttributeMaxDynamicSharedMemorySize, GSMEM);
    cudaFuncSetAttribute(mma_gemm<2>, cudaFuncAttributeMaxDynamicSharedMemorySize, GSMEM);

    init_kernel<<<512, 256>>>();
    pad_pack<<<8192, 256>>>(inputs);
    wprep<<<8192, 256>>>(convk, wk_f, wk_b);

    const size_t wcs = (size_t)512 * 2560;
    dim3 gc(D_ / BN, T_ / BM, B_);           // (4, 8, 64)
    mma_gemm<0><<<gc, 256, GSMEM>>>(x0, wch + 0 * wcs, wcl + 0 * wcs, KTAP * D_,
                                    convb + 0 * D_, bng + 0 * D_, bnb + 0 * D_,
                                    bnm + 0 * D_, bnv + 0 * D_, x1, nullptr);
    mma_gemm<0><<<gc, 256, GSMEM>>>(x1, wch + 1 * wcs, wcl + 1 * wcs, KTAP * D_,
                                    convb + 1 * D_, bng + 1 * D_, bnb + 1 * D_,
                                    bnm + 1 * D_, bnv + 1 * D_, x0, nullptr);
    mma_gemm<0><<<gc, 256, GSMEM>>>(x0, wch + 2 * wcs, wcl + 2 * wcs, KTAP * D_,
                                    convb + 2 * D_, bng + 2 * D_, bnb + 2 * D_,
                                    bnm + 2 * D_, bnv + 2 * D_, x1, nullptr);

    const size_t wls = (size_t)1024 * 512;
    dim3 gl(G4_ / BN, T_ / BM, B_);          // (8, 8, 64)
    mma_gemm<1><<<gl, 256, GSMEM>>>(x1 + 2 * D_, wlh + 0 * wls, wll + 0 * wls, D_,
                                    bi_f, bng, bnb, bnm, bnv, nullptr, pre_f);
    mma_gemm<2><<<gl, 256, GSMEM>>>(x1 + 2 * D_, wlh + 1 * wls, wll + 1 * wls, D_,
                                    bi_b, bng, bnb, bnm, bnv, nullptr, pre_b);

    const int lstm_smem = (4096 + 64 * 260) * (int)sizeof(float);
    cudaFuncSetAttribute(lstm_kernel, cudaFuncAttributeMaxDynamicSharedMemorySize, lstm_smem);
    lstm_kernel<<<2 * RNN_CTAS, 256, lstm_smem>>>(pre_f, pre_b, wr_f, wr_b, out);
}

// round 12
// speedup vs baseline: 1.1766x; 1.1766x over previous
#include <cuda_runtime.h>
#include <cuda_fp16.h>
#include <cstdint>
#include <math.h>

#define B_    64
#define T_    1024
#define D_    512
#define KTAP  5
#define U_    256
#define G4_   1024
#define TP_   (T_ + 4)
#define XPD_  (TP_ * D_)
#define RNN_CTAS 64

#define BM    128
#define BN    128
#define KC    32                 // fp16 k per chunk
#define ROWB  80                 // smem row stride (bytes) -> conflict-free ldmatrix
#define TILEB (128 * ROWB)       // 10240 B per tile
#define STAGEB (3 * TILEB)       // A, BH, BL
#define NSTG  3
#define GSMEM (NSTG * STAGEB)    // 90 KB -> 2 CTAs/SM

// ---------------- scratch ----------------
__device__ uint16_t g_x0[(size_t)B_ * XPD_];        // fp16 activation planes
__device__ uint16_t g_x1[(size_t)B_ * XPD_];
__device__ uint16_t g_wch[(size_t)3 * 512 * 2560];  // conv weights hi [i][n][kk]
__device__ uint16_t g_wcl[(size_t)3 * 512 * 2560];  // conv weights lo
__device__ uint16_t g_wlh[(size_t)2 * 1024 * 512];  // lstm kernels hi [dir][n][d]
__device__ uint16_t g_wll[(size_t)2 * 1024 * 512];  // lstm kernels lo
__device__ float    g_pre_f[(size_t)T_ * B_ * G4_];
__device__ float    g_pre_b[(size_t)T_ * B_ * G4_];
__device__ float    g_h[2][2][B_ * U_];
__device__ unsigned g_bar[2];

// ---------------- helpers ----------------
__device__ __forceinline__ uint32_t smem_u32(const void* p) {
    uint32_t a;
    asm("{ .reg .u64 t; cvta.to.shared.u64 t, %1; cvt.u32.u64 %0, t; }" : "=r"(a) : "l"(p));
    return a;
}
__device__ __forceinline__ uint16_t f2h(float v) {
    return __half_as_ushort(__float2half(v));
}
__device__ __forceinline__ void split_h16(float v, uint16_t& h, uint16_t& l) {
    __half hh = __float2half(v);
    float hf = __half2float(hh);
    h = __half_as_ushort(hh);
    l = __half_as_ushort(__float2half(v - hf));
}
#define CP16(dst, src) \
    asm volatile("cp.async.cg.shared.global [%0], [%1], 16;" :: "r"(dst), "l"(src))
#define CP_COMMIT() asm volatile("cp.async.commit_group;" ::: "memory")
#define CP_WAIT(N)  asm volatile("cp.async.wait_group %0;" :: "n"(N) : "memory")
#define LDM_X4(R0, R1, R2, R3, ADDR)                                            \
    asm volatile("ldmatrix.sync.aligned.m8n8.x4.shared.b16 {%0,%1,%2,%3}, [%4];"\
        : "=r"(R0), "=r"(R1), "=r"(R2), "=r"(R3) : "r"(ADDR))
__device__ __forceinline__ void mma_f16(float* c, const uint32_t* a, const uint32_t* b) {
    asm volatile(
        "mma.sync.aligned.m16n8k16.row.col.f32.f16.f16.f32 "
        "{%0,%1,%2,%3}, {%4,%5,%6,%7}, {%8,%9}, {%0,%1,%2,%3};"
        : "+f"(c[0]), "+f"(c[1]), "+f"(c[2]), "+f"(c[3])
        : "r"(a[0]), "r"(a[1]), "r"(a[2]), "r"(a[3]), "r"(b[0]), "r"(b[1]));
}
// packed fp32x2 (Blackwell)
#define PACK2(d, lo, hi) asm("mov.b64 %0, {%1, %2};" : "=l"(d) : "f"(lo), "f"(hi))
#define UNPACK2(lo, hi, s) asm("mov.b64 {%0, %1}, %2;" : "=f"(lo), "=f"(hi) : "l"(s))
#define FMA2(d, a, b) asm("fma.rn.f32x2 %0, %1, %2, %0;" : "+l"(d) : "l"(a), "l"(b))

// ---------------- fused prep: halos + h/bar zero + input pack + weight prep ----------------
__global__ void prep_kernel(const float* __restrict__ in,
                            const float* __restrict__ convk,
                            const float* __restrict__ wkf,
                            const float* __restrict__ wkb) {
    const size_t stride = (size_t)gridDim.x * blockDim.x;
    const size_t tid0 = (size_t)blockIdx.x * blockDim.x + threadIdx.x;

    // halos of both planes
    for (size_t idx = tid0; idx < (size_t)B_ * 4 * D_; idx += stride) {
        int b = (int)(idx / (4 * D_));
        int r = (int)((idx / D_) & 3);
        int d = (int)(idx % D_);
        int row = (r < 2) ? r : (TP_ - 4 + r);
        size_t o = (size_t)b * XPD_ + (size_t)row * D_ + d;
        g_x0[o] = 0; g_x1[o] = 0;
    }
    // h slots + barrier counters
    for (size_t idx = tid0; idx < 2 * 2 * B_ * U_; idx += stride)
        ((float*)g_h)[idx] = 0.f;
    if (tid0 < 2) g_bar[tid0] = 0u;

    // input pack (fp16)
    for (size_t idx = tid0; idx < (size_t)B_ * T_ * D_; idx += stride) {
        size_t b = idx / ((size_t)T_ * D_);
        size_t r = idx % ((size_t)T_ * D_);
        size_t t = r / D_, d = r % D_;
        g_x0[b * XPD_ + (t + 2) * D_ + d] = f2h(in[idx]);
    }

    // weight transpose + hi/lo split
    const size_t CONVN = (size_t)3 * 512 * 2560;
    const size_t LSTMN = (size_t)1024 * 512;
    for (size_t idx = tid0; idx < CONVN + 2 * LSTMN; idx += stride) {
        uint16_t h, l;
        if (idx < CONVN) {
            size_t i = idx / ((size_t)512 * 2560);
            size_t r = idx % ((size_t)512 * 2560);
            size_t n = r / 2560, kk = r % 2560;
            size_t tap = kk >> 9, din = kk & 511;
            split_h16(convk[(((i * KTAP + tap) * D_) + din) * D_ + n], h, l);
            g_wch[idx] = h; g_wcl[idx] = l;
        } else if (idx < CONVN + LSTMN) {
            size_t j = idx - CONVN;
            size_t n = j >> 9, d = j & 511;
            split_h16(wkf[d * G4_ + n], h, l);
            g_wlh[j] = h; g_wll[j] = l;
        } else {
            size_t j = idx - CONVN - LSTMN;
            size_t n = j >> 9, d = j & 511;
            split_h16(wkb[d * G4_ + n], h, l);
            g_wlh[LSTMN + j] = h; g_wll[LSTMN + j] = l;
        }
    }
}

// ---------------- fp16 2-term warp-MMA conv GEMM (bias+BN+ReLU epilogue) ----------------
__global__ __launch_bounds__(256, 2) void mma_gemm_conv(
    const uint16_t* __restrict__ Ap,
    const uint16_t* __restrict__ Bh, const uint16_t* __restrict__ Bl,
    const float* __restrict__ bias,
    const float* __restrict__ bng, const float* __restrict__ bnb,
    const float* __restrict__ bnm, const float* __restrict__ bnv,
    uint16_t* __restrict__ Cp)
{
    extern __shared__ char smraw[];
    const uint32_t sbase = smem_u32(smraw);
    const int KKtot = KTAP * D_;

    const int tid = threadIdx.x;
    const int wid = tid >> 5, lane = tid & 31;
    const int bz = blockIdx.z;
    const int t0 = blockIdx.y * BM;
    const int n0 = blockIdx.x * BN;
    const int wm = wid & 1;
    const int wn = wid >> 1;

    const uint32_t a_off = (uint32_t)((wm * 64 + (lane & 15)) * ROWB + (lane >> 4) * 16);
    const uint32_t b_off = (uint32_t)((wn * 32 + (lane & 7) + ((lane >> 4) << 3)) * ROWB
                                      + ((lane >> 3) & 1) * 16);

    const uint16_t* Ab = Ap + (size_t)bz * XPD_;
    const int NCH = KKtot / KC;

    float cacc[4][4][4];
#pragma unroll
    for (int i = 0; i < 4; i++)
#pragma unroll
        for (int j = 0; j < 4; j++)
#pragma unroll
            for (int q = 0; q < 4; q++) cacc[i][j][q] = 0.f;

    auto issue = [&](int cc) {
        const int st = cc % NSTG;
        const int kk0 = cc * KC;
        const int tap = kk0 >> 9;
        const int d0 = kk0 & 511;
        const uint32_t sb = sbase + st * STAGEB;
#pragma unroll
        for (int half = 0; half < 2; half++) {
            const int s = tid + half * 256;
            const int row = s >> 2, seg = s & 3;
            const uint32_t doff = (uint32_t)(row * ROWB + seg * 16);
            const size_t aoff = (size_t)(t0 + row + tap) * D_ + d0 + seg * 8;
            const size_t boff = (size_t)(n0 + row) * KKtot + kk0 + seg * 8;
            CP16(sb + doff,             Ab + aoff);
            CP16(sb + TILEB + doff,     Bh + boff);
            CP16(sb + 2 * TILEB + doff, Bl + boff);
        }
        CP_COMMIT();
    };

    auto compute = [&](int st) {
        const uint32_t SB = sbase + st * STAGEB;
#pragma unroll
        for (int k16 = 0; k16 < 2; k16++) {
            const uint32_t kof = k16 * 32;
            uint32_t bh[4][2], bl[4][2];
#pragma unroll
            for (int nfp = 0; nfp < 2; nfp++) {
                uint32_t bd = SB + TILEB + b_off + nfp * (16 * ROWB) + kof;
                LDM_X4(bh[2 * nfp][0], bh[2 * nfp][1], bh[2 * nfp + 1][0], bh[2 * nfp + 1][1], bd);
                LDM_X4(bl[2 * nfp][0], bl[2 * nfp][1], bl[2 * nfp + 1][0], bl[2 * nfp + 1][1], bd + TILEB);
            }
#pragma unroll
            for (int mf = 0; mf < 4; mf++) {
                uint32_t af[4];
                uint32_t ad = SB + a_off + mf * (16 * ROWB) + kof;
                LDM_X4(af[0], af[1], af[2], af[3], ad);
#pragma unroll
                for (int nf = 0; nf < 4; nf++) {
                    mma_f16(cacc[mf][nf], af, bh[nf]);
                    mma_f16(cacc[mf][nf], af, bl[nf]);
                }
            }
        }
    };

    issue(0);
    issue(1);
    for (int cc = 0; cc < NCH; cc++) {
        CP_WAIT(1);
        __syncthreads();
        if (cc + 2 < NCH) issue(cc + 2);
        else CP_COMMIT();
        compute(cc % NSTG);
    }

    const int r0 = lane >> 2;
    const int cq = (lane & 3) * 2;
    float mul0[4], mul1[4], add0[4], add1[4];
#pragma unroll
    for (int nf = 0; nf < 4; nf++) {
        int n = n0 + wn * 32 + nf * 8 + cq;
        float b0 = __ldg(&bias[n]), b1 = __ldg(&bias[n + 1]);
        float s0 = __ldg(&bng[n]) * rsqrtf(__ldg(&bnv[n]) + 1e-3f);
        float s1 = __ldg(&bng[n + 1]) * rsqrtf(__ldg(&bnv[n + 1]) + 1e-3f);
        mul0[nf] = s0; mul1[nf] = s1;
        add0[nf] = s0 * (b0 - __ldg(&bnm[n])) + __ldg(&bnb[n]);
        add1[nf] = s1 * (b1 - __ldg(&bnm[n + 1])) + __ldg(&bnb[n + 1]);
    }
#pragma unroll
    for (int mf = 0; mf < 4; mf++) {
#pragma unroll
        for (int half = 0; half < 2; half++) {
            int m = wm * 64 + mf * 16 + r0 + half * 8;
#pragma unroll
            for (int nf = 0; nf < 4; nf++) {
                float v0 = fmaxf(fmaf(cacc[mf][nf][2 * half + 0], mul0[nf], add0[nf]), 0.f);
                float v1 = fmaxf(fmaf(cacc[mf][nf][2 * half + 1], mul1[nf], add1[nf]), 0.f);
                int nc = n0 + wn * 32 + nf * 8 + cq;
                size_t off = (size_t)bz * XPD_ + (size_t)(t0 + m + 2) * D_ + nc;
                *(uint32_t*)(Cp + off) = (uint32_t)f2h(v0) | ((uint32_t)f2h(v1) << 16);
            }
        }
    }
}

// ---------------- fused fw+bw LSTM-pre GEMM (one launch, grid.x = 16) ----------------
__global__ __launch_bounds__(256, 2) void mma_gemm_pre(
    const uint16_t* __restrict__ Ap,
    const uint16_t* __restrict__ Bhf, const uint16_t* __restrict__ Blf,
    const uint16_t* __restrict__ Bhb, const uint16_t* __restrict__ Blb,
    const float* __restrict__ bias_f, const float* __restrict__ bias_b,
    float* __restrict__ pre_f, float* __restrict__ pre_b)
{
    extern __shared__ char smraw[];
    const uint32_t sbase = smem_u32(smraw);
    const int KKtot = D_;

    const int tid = threadIdx.x;
    const int wid = tid >> 5, lane = tid & 31;
    const int bz = blockIdx.z;
    const int t0 = blockIdx.y * BM;
    const int fw = (blockIdx.x < 8);
    const int n0 = (blockIdx.x & 7) * BN;
    const int wm = wid & 1;
    const int wn = wid >> 1;

    const uint16_t* Bh = fw ? Bhf : Bhb;
    const uint16_t* Bl = fw ? Blf : Blb;
    const float* bias = fw ? bias_f : bias_b;
    float* Cf = fw ? pre_f : pre_b;

    const uint32_t a_off = (uint32_t)((wm * 64 + (lane & 15)) * ROWB + (lane >> 4) * 16);
    const uint32_t b_off = (uint32_t)((wn * 32 + (lane & 7) + ((lane >> 4) << 3)) * ROWB
                                      + ((lane >> 3) & 1) * 16);

    const uint16_t* Ab = Ap + (size_t)bz * XPD_;
    const int NCH = KKtot / KC;   // 16

    float cacc[4][4][4];
#pragma unroll
    for (int i = 0; i < 4; i++)
#pragma unroll
        for (int j = 0; j < 4; j++)
#pragma unroll
            for (int q = 0; q < 4; q++) cacc[i][j][q] = 0.f;

    auto issue = [&](int cc) {
        const int st = cc % NSTG;
        const int kk0 = cc * KC;
        const uint32_t sb = sbase + st * STAGEB;
#pragma unroll
        for (int half = 0; half < 2; half++) {
            const int s = tid + half * 256;
            const int row = s >> 2, seg = s & 3;
            const uint32_t doff = (uint32_t)(row * ROWB + seg * 16);
            const size_t aoff = (size_t)(t0 + row) * D_ + kk0 + seg * 8;
            const size_t boff = (size_t)(n0 + row) * KKtot + kk0 + seg * 8;
            CP16(sb + doff,             Ab + aoff);
            CP16(sb + TILEB + doff,     Bh + boff);
            CP16(sb + 2 * TILEB + doff, Bl + boff);
        }
        CP_COMMIT();
    };

    auto compute = [&](int st) {
        const uint32_t SB = sbase + st * STAGEB;
#pragma unroll
        for (int k16 = 0; k16 < 2; k16++) {
            const uint32_t kof = k16 * 32;
            uint32_t bh[4][2], bl[4][2];
#pragma unroll
            for (int nfp = 0; nfp < 2; nfp++) {
                uint32_t bd = SB + TILEB + b_off + nfp * (16 * ROWB) + kof;
                LDM_X4(bh[2 * nfp][0], bh[2 * nfp][1], bh[2 * nfp + 1][0], bh[2 * nfp + 1][1], bd);
                LDM_X4(bl[2 * nfp][0], bl[2 * nfp][1], bl[2 * nfp + 1][0], bl[2 * nfp + 1][1], bd + TILEB);
            }
#pragma unroll
            for (int mf = 0; mf < 4; mf++) {
                uint32_t af[4];
                uint32_t ad = SB + a_off + mf * (16 * ROWB) + kof;
                LDM_X4(af[0], af[1], af[2], af[3], ad);
#pragma unroll
                for (int nf = 0; nf < 4; nf++) {
                    mma_f16(cacc[mf][nf], af, bh[nf]);
                    mma_f16(cacc[mf][nf], af, bl[nf]);
                }
            }
        }
    };

    issue(0);
    issue(1);
    for (int cc = 0; cc < NCH; cc++) {
        CP_WAIT(1);
        __syncthreads();
        if (cc + 2 < NCH) issue(cc + 2);
        else CP_COMMIT();
        compute(cc % NSTG);
    }

    const int r0 = lane >> 2;
    const int cq = (lane & 3) * 2;
    float add0[4], add1[4];
#pragma unroll
    for (int nf = 0; nf < 4; nf++) {
        int n = n0 + wn * 32 + nf * 8 + cq;
        add0[nf] = __ldg(&bias[n]);
        add1[nf] = __ldg(&bias[n + 1]);
    }
#pragma unroll
    for (int mf = 0; mf < 4; mf++) {
#pragma unroll
        for (int half = 0; half < 2; half++) {
            int m = wm * 64 + mf * 16 + r0 + half * 8;
            int t = t0 + m;
            size_t rowoff = fw ? ((size_t)t * B_ + bz) * G4_
                               : ((size_t)(T_ - 1 - t) * B_ + bz) * G4_;
#pragma unroll
            for (int nf = 0; nf < 4; nf++) {
                int nc = n0 + wn * 32 + nf * 8 + cq;
                float v0 = cacc[mf][nf][2 * half + 0] + add0[nf];
                float v1 = cacc[mf][nf][2 * half + 1] + add1[nf];
                *(float2*)(Cf + rowoff + nc) = make_float2(v0, v1);
            }
        }
    }
}

// ---------------- persistent bi-LSTM recurrence (byte-exact R8 form) ----------------
__global__ __launch_bounds__(256) void lstm_kernel(
    const float* __restrict__ pre_f, const float* __restrict__ pre_b,
    const float* __restrict__ wr_f,  const float* __restrict__ wr_b,
    float* __restrict__ out)
{
    extern __shared__ float sm[];
    float* sW = sm;            // [128][4][4][2] = 4096 floats
    float* sH = sm + 4096;     // [64][260]

    const int bx  = blockIdx.x;
    const int dir = bx >> 6;
    const int u0  = (bx & 63) << 2;
    const float* pre = dir ? pre_b : pre_f;
    const float* Wr  = dir ? wr_b  : wr_f;
    unsigned* bar = &g_bar[dir];

    const int tid = threadIdx.x;
    const int b = tid >> 2, q = tid & 3, u = u0 + q;

    for (int idx = tid; idx < 4096; idx += 256) {
        int par = idx & 1;
        int rest = idx >> 1;
        int g = rest & 3, qq = (rest >> 2) & 3, k2 = rest >> 4;
        int k = 2 * k2 + par;
        sW[idx] = Wr[(size_t)k * G4_ + g * U_ + u0 + qq];
    }

    float c = 0.f;
    float* h0 = &g_h[dir][0][0];
    float* h1 = &g_h[dir][1][0];
    __syncthreads();

    const uint64_t* wbase = (const uint64_t*)(sW) + q * 4;

    for (int t = 0; t < T_; t++) {
        const float* p = pre + ((size_t)t * B_ + b) * G4_ + u;
        float z0 = __ldg(&p[0]);
        float z1 = __ldg(&p[U_]);
        float z2 = __ldg(&p[2 * U_]);
        float z3 = __ldg(&p[3 * U_]);

        const float* hr = ((t + 1) & 1) ? h1 : h0;
        for (int idx = tid * 4; idx < B_ * U_; idx += 1024) {
            float4 v = __ldcg((const float4*)(hr + idx));
            int row = idx >> 8, col = idx & 255;
            *(float4*)&sH[row * 260 + col] = v;
        }
        __syncthreads();

        uint64_t ai, af, ag, ao;
        PACK2(ai, z0, 0.f);
        PACK2(af, z1, 0.f);
        PACK2(ag, z2, 0.f);
        PACK2(ao, z3, 0.f);

        const float* hrow = &sH[b * 260];
#pragma unroll 8
        for (int k2 = 0; k2 < U_ / 2; k2++) {
            uint64_t h2 = *(const uint64_t*)(hrow + k2 * 2);
            const uint64_t* wp = wbase + k2 * 16;
            FMA2(ai, h2, wp[0]);
            FMA2(af, h2, wp[1]);
            FMA2(ag, h2, wp[2]);
            FMA2(ao, h2, wp[3]);
        }
        float e0, e1;
        UNPACK2(e0, e1, ai); z0 = e0 + e1;
        UNPACK2(e0, e1, af); z1 = e0 + e1;
        UNPACK2(e0, e1, ag); z2 = e0 + e1;
        UNPACK2(e0, e1, ao); z3 = e0 + e1;

        float ig = 1.f / (1.f + __expf(-z0));
        float fg = 1.f / (1.f + __expf(-z1));
        float gg = tanhf(z2);
        float og = 1.f / (1.f + __expf(-z3));
        c = fg * c + ig * gg;
        float h = og * tanhf(c);

        float* hw = (t & 1) ? h1 : h0;
        hw[b * U_ + u] = h;
        int tout = dir ? (T_ - 1 - t) : t;
        out[((size_t)b * T_ + tout) * (2 * U_) + dir * U_ + u] = h;

        __syncthreads();
        if (tid == 0) {
            __threadfence();
            atomicAdd(bar, 1u);
            unsigned target = (unsigned)(t + 1) * RNN_CTAS;
            unsigned v;
            do {
                asm volatile("ld.global.acquire.gpu.u32 %0, [%1];" : "=r"(v) : "l"(bar));
            } while (v < target);
        }
        __syncthreads();
    }
}

// ---------------- launcher ----------------
extern "C" void kernel_launch(void* const* d_in, const int* in_sizes, int n_in,
                              void* d_out, int out_size)
{
    const float* inputs = (const float*)d_in[0];
    const float* convk  = (const float*)d_in[1];
    const float* convb  = (const float*)d_in[2];
    const float* bng    = (const float*)d_in[3];
    const float* bnb    = (const float*)d_in[4];
    const float* bnm    = (const float*)d_in[5];
    const float* bnv    = (const float*)d_in[6];
    const float* wk_f   = (const float*)d_in[7];
    const float* wr_f   = (const float*)d_in[8];
    const float* bi_f   = (const float*)d_in[9];
    const float* wk_b   = (const float*)d_in[10];
    const float* wr_b   = (const float*)d_in[11];
    const float* bi_b   = (const float*)d_in[12];
    float* out = (float*)d_out;

    uint16_t *x0, *x1, *wch, *wcl, *wlh, *wll;
    float *pre_f, *pre_b;
    cudaGetSymbolAddress((void**)&x0, g_x0);
    cudaGetSymbolAddress((void**)&x1, g_x1);
    cudaGetSymbolAddress((void**)&wch, g_wch);
    cudaGetSymbolAddress((void**)&wcl, g_wcl);
    cudaGetSymbolAddress((void**)&wlh, g_wlh);
    cudaGetSymbolAddress((void**)&wll, g_wll);
    cudaGetSymbolAddress((void**)&pre_f, g_pre_f);
    cudaGetSymbolAddress((void**)&pre_b, g_pre_b);

    cudaFuncSetAttribute(mma_gemm_conv, cudaFuncAttributeMaxDynamicSharedMemorySize, GSMEM);
    cudaFuncSetAttribute(mma_gemm_pre,  cudaFuncAttributeMaxDynamicSharedMemorySize, GSMEM);

    // launch 0: fused prep
    prep_kernel<<<8192, 256>>>(inputs, convk, wk_f, wk_b);

    // launches 1-3: convs
    const size_t wcs = (size_t)512 * 2560;
    dim3 gc(D_ / BN, T_ / BM, B_);           // (4, 8, 64)
    mma_gemm_conv<<<gc, 256, GSMEM>>>(x0, wch + 0 * wcs, wcl + 0 * wcs,
                                      convb + 0 * D_, bng + 0 * D_, bnb + 0 * D_,
                                      bnm + 0 * D_, bnv + 0 * D_, x1);
    mma_gemm_conv<<<gc, 256, GSMEM>>>(x1, wch + 1 * wcs, wcl + 1 * wcs,
                                      convb + 1 * D_, bng + 1 * D_, bnb + 1 * D_,
                                      bnm + 1 * D_, bnv + 1 * D_, x0);
    mma_gemm_conv<<<gc, 256, GSMEM>>>(x0, wch + 2 * wcs, wcl + 2 * wcs,
                                      convb + 2 * D_, bng + 2 * D_, bnb + 2 * D_,
                                      bnm + 2 * D_, bnv + 2 * D_, x1);

    // launch 4: fused fw+bw LSTM-pre GEMM
    const size_t wls = (size_t)1024 * 512;
    dim3 gl(16, T_ / BM, B_);                // (16, 8, 64): x<8 fw, x>=8 bw
    mma_gemm_pre<<<gl, 256, GSMEM>>>(x1 + 2 * D_,
                                     wlh + 0 * wls, wll + 0 * wls,
                                     wlh + 1 * wls, wll + 1 * wls,
                                     bi_f, bi_b, pre_f, pre_b);

    // launch 5: recurrence (now inside the ncu -s 5 -c 1 window)
    const int lstm_smem = (4096 + 64 * 260) * (int)sizeof(float);
    cudaFuncSetAttribute(lstm_kernel, cudaFuncAttributeMaxDynamicSharedMemorySize, lstm_smem);
    lstm_kernel<<<2 * RNN_CTAS, 256, lstm_smem>>>(pre_f, pre_b, wr_f, wr_b, out);
}

// round 13
// speedup vs baseline: 1.3207x; 1.1225x over previous
#include <cuda_runtime.h>
#include <cuda_fp16.h>
#include <cstdint>
#include <math.h>

#define B_    64
#define T_    1024
#define D_    512
#define KTAP  5
#define U_    256
#define G4_   1024
#define TP_   (T_ + 4)
#define XPD_  (TP_ * D_)

#define BM    128
#define BN    128
#define KC    32
#define ROWB  80
#define TILEB (128 * ROWB)
#define STAGEB (3 * TILEB)
#define NSTG  3
#define GSMEM (NSTG * STAGEB)

// lstm tc kernel tiles: 64 rows x 80B = 5120 B
#define LTILE 5120
#define LSMEM (32 * LTILE)       // 16 H tiles + 16 W tiles = 163840 B

// ---------------- scratch ----------------
__device__ uint16_t g_x0[(size_t)B_ * XPD_];
__device__ uint16_t g_x1[(size_t)B_ * XPD_];
__device__ uint16_t g_wch[(size_t)3 * 512 * 2560];
__device__ uint16_t g_wcl[(size_t)3 * 512 * 2560];
__device__ uint16_t g_wlh[(size_t)2 * 1024 * 512];
__device__ uint16_t g_wll[(size_t)2 * 1024 * 512];
__device__ uint16_t g_wrh[(size_t)2 * 1024 * 256];  // recurrent W, [dir][colp][k]
__device__ uint16_t g_wrl[(size_t)2 * 1024 * 256];
__device__ float    g_pre_f[(size_t)T_ * B_ * G4_]; // colp-permuted [t][b][4u+g]
__device__ float    g_pre_b[(size_t)T_ * B_ * G4_];
__device__ uint16_t g_hh[2][2][B_ * U_];            // h fp16 hi [dir][slot][b*256+u]
__device__ uint16_t g_hl[2][2][B_ * U_];
__device__ unsigned g_bar[2];

// ---------------- helpers ----------------
__device__ __forceinline__ uint32_t smem_u32(const void* p) {
    uint32_t a;
    asm("{ .reg .u64 t; cvta.to.shared.u64 t, %1; cvt.u32.u64 %0, t; }" : "=r"(a) : "l"(p));
    return a;
}
__device__ __forceinline__ uint16_t f2h(float v) {
    return __half_as_ushort(__float2half(v));
}
__device__ __forceinline__ void split_h16(float v, uint16_t& h, uint16_t& l) {
    __half hh = __float2half(v);
    float hf = __half2float(hh);
    h = __half_as_ushort(hh);
    l = __half_as_ushort(__float2half(v - hf));
}
#define CP16(dst, src) \
    asm volatile("cp.async.cg.shared.global [%0], [%1], 16;" :: "r"(dst), "l"(src))
#define CP_COMMIT() asm volatile("cp.async.commit_group;" ::: "memory")
#define CP_WAIT(N)  asm volatile("cp.async.wait_group %0;" :: "n"(N) : "memory")
#define LDM_X4(R0, R1, R2, R3, ADDR)                                            \
    asm volatile("ldmatrix.sync.aligned.m8n8.x4.shared.b16 {%0,%1,%2,%3}, [%4];"\
        : "=r"(R0), "=r"(R1), "=r"(R2), "=r"(R3) : "r"(ADDR))
__device__ __forceinline__ void mma_f16(float* c, const uint32_t* a, const uint32_t* b) {
    asm volatile(
        "mma.sync.aligned.m16n8k16.row.col.f32.f16.f16.f32 "
        "{%0,%1,%2,%3}, {%4,%5,%6,%7}, {%8,%9}, {%0,%1,%2,%3};"
        : "+f"(c[0]), "+f"(c[1]), "+f"(c[2]), "+f"(c[3])
        : "r"(a[0]), "r"(a[1]), "r"(a[2]), "r"(a[3]), "r"(b[0]), "r"(b[1]));
}

// ---------------- fused prep ----------------
__global__ void prep_kernel(const float* __restrict__ in,
                            const float* __restrict__ convk,
                            const float* __restrict__ wkf,
                            const float* __restrict__ wkb,
                            const float* __restrict__ wrf,
                            const float* __restrict__ wrb) {
    const size_t stride = (size_t)gridDim.x * blockDim.x;
    const size_t tid0 = (size_t)blockIdx.x * blockDim.x + threadIdx.x;

    for (size_t idx = tid0; idx < (size_t)B_ * 4 * D_; idx += stride) {
        int b = (int)(idx / (4 * D_));
        int r = (int)((idx / D_) & 3);
        int d = (int)(idx % D_);
        int row = (r < 2) ? r : (TP_ - 4 + r);
        size_t o = (size_t)b * XPD_ + (size_t)row * D_ + d;
        g_x0[o] = 0; g_x1[o] = 0;
    }
    // zero h buffers (as uint32 words)
    for (size_t idx = tid0; idx < (size_t)2 * 2 * B_ * U_ / 2; idx += stride) {
        ((uint32_t*)g_hh)[idx] = 0u;
        ((uint32_t*)g_hl)[idx] = 0u;
    }
    if (tid0 < 2) g_bar[tid0] = 0u;

    for (size_t idx = tid0; idx < (size_t)B_ * T_ * D_; idx += stride) {
        size_t b = idx / ((size_t)T_ * D_);
        size_t r = idx % ((size_t)T_ * D_);
        size_t t = r / D_, d = r % D_;
        g_x0[b * XPD_ + (t + 2) * D_ + d] = f2h(in[idx]);
    }

    const size_t CONVN = (size_t)3 * 512 * 2560;
    const size_t LSTMN = (size_t)1024 * 512;
    for (size_t idx = tid0; idx < CONVN + 2 * LSTMN; idx += stride) {
        uint16_t h, l;
        if (idx < CONVN) {
            size_t i = idx / ((size_t)512 * 2560);
            size_t r = idx % ((size_t)512 * 2560);
            size_t n = r / 2560, kk = r % 2560;
            size_t tap = kk >> 9, din = kk & 511;
            split_h16(convk[(((i * KTAP + tap) * D_) + din) * D_ + n], h, l);
            g_wch[idx] = h; g_wcl[idx] = l;
        } else if (idx < CONVN + LSTMN) {
            size_t j = idx - CONVN;
            size_t n = j >> 9, d = j & 511;
            split_h16(wkf[d * G4_ + n], h, l);
            g_wlh[j] = h; g_wll[j] = l;
        } else {
            size_t j = idx - CONVN - LSTMN;
            size_t n = j >> 9, d = j & 511;
            split_h16(wkb[d * G4_ + n], h, l);
            g_wlh[LSTMN + j] = h; g_wll[LSTMN + j] = l;
        }
    }

    // recurrent weights: Wt[dir][colp][k], colp = 4u+g
    const size_t WRN = (size_t)2 * 1024 * 256;
    for (size_t idx = tid0; idx < WRN; idx += stride) {
        size_t dir = idx >> 18;
        size_t r = idx & 262143;
        size_t colp = r >> 8, k = r & 255;
        size_t u = colp >> 2, g = colp & 3;
        const float* wr = dir ? wrb : wrf;
        uint16_t h, l;
        split_h16(wr[k * G4_ + g * U_ + u], h, l);
        g_wrh[idx] = h; g_wrl[idx] = l;
    }
}

// ---------------- fp16 2-term warp-MMA conv GEMM ----------------
__global__ __launch_bounds__(256, 2) void mma_gemm_conv(
    const uint16_t* __restrict__ Ap,
    const uint16_t* __restrict__ Bh, const uint16_t* __restrict__ Bl,
    const float* __restrict__ bias,
    const float* __restrict__ bng, const float* __restrict__ bnb,
    const float* __restrict__ bnm, const float* __restrict__ bnv,
    uint16_t* __restrict__ Cp)
{
    extern __shared__ char smraw[];
    const uint32_t sbase = smem_u32(smraw);
    const int KKtot = KTAP * D_;

    const int tid = threadIdx.x;
    const int wid = tid >> 5, lane = tid & 31;
    const int bz = blockIdx.z;
    const int t0 = blockIdx.y * BM;
    const int n0 = blockIdx.x * BN;
    const int wm = wid & 1;
    const int wn = wid >> 1;

    const uint32_t a_off = (uint32_t)((wm * 64 + (lane & 15)) * ROWB + (lane >> 4) * 16);
    const uint32_t b_off = (uint32_t)((wn * 32 + (lane & 7) + ((lane >> 4) << 3)) * ROWB
                                      + ((lane >> 3) & 1) * 16);

    const uint16_t* Ab = Ap + (size_t)bz * XPD_;
    const int NCH = KKtot / KC;

    float cacc[4][4][4];
#pragma unroll
    for (int i = 0; i < 4; i++)
#pragma unroll
        for (int j = 0; j < 4; j++)
#pragma unroll
            for (int q = 0; q < 4; q++) cacc[i][j][q] = 0.f;

    auto issue = [&](int cc) {
        const int st = cc % NSTG;
        const int kk0 = cc * KC;
        const int tap = kk0 >> 9;
        const int d0 = kk0 & 511;
        const uint32_t sb = sbase + st * STAGEB;
#pragma unroll
        for (int half = 0; half < 2; half++) {
            const int s = tid + half * 256;
            const int row = s >> 2, seg = s & 3;
            const uint32_t doff = (uint32_t)(row * ROWB + seg * 16);
            const size_t aoff = (size_t)(t0 + row + tap) * D_ + d0 + seg * 8;
            const size_t boff = (size_t)(n0 + row) * KKtot + kk0 + seg * 8;
            CP16(sb + doff,             Ab + aoff);
            CP16(sb + TILEB + doff,     Bh + boff);
            CP16(sb + 2 * TILEB + doff, Bl + boff);
        }
        CP_COMMIT();
    };

    auto compute = [&](int st) {
        const uint32_t SB = sbase + st * STAGEB;
#pragma unroll
        for (int k16 = 0; k16 < 2; k16++) {
            const uint32_t kof = k16 * 32;
            uint32_t bh[4][2], bl[4][2];
#pragma unroll
            for (int nfp = 0; nfp < 2; nfp++) {
                uint32_t bd = SB + TILEB + b_off + nfp * (16 * ROWB) + kof;
                LDM_X4(bh[2 * nfp][0], bh[2 * nfp][1], bh[2 * nfp + 1][0], bh[2 * nfp + 1][1], bd);
                LDM_X4(bl[2 * nfp][0], bl[2 * nfp][1], bl[2 * nfp + 1][0], bl[2 * nfp + 1][1], bd + TILEB);
            }
#pragma unroll
            for (int mf = 0; mf < 4; mf++) {
                uint32_t af[4];
                uint32_t ad = SB + a_off + mf * (16 * ROWB) + kof;
                LDM_X4(af[0], af[1], af[2], af[3], ad);
#pragma unroll
                for (int nf = 0; nf < 4; nf++) {
                    mma_f16(cacc[mf][nf], af, bh[nf]);
                    mma_f16(cacc[mf][nf], af, bl[nf]);
                }
            }
        }
    };

    issue(0);
    issue(1);
    for (int cc = 0; cc < NCH; cc++) {
        CP_WAIT(1);
        __syncthreads();
        if (cc + 2 < NCH) issue(cc + 2);
        else CP_COMMIT();
        compute(cc % NSTG);
    }

    const int r0 = lane >> 2;
    const int cq = (lane & 3) * 2;
    float mul0[4], mul1[4], add0[4], add1[4];
#pragma unroll
    for (int nf = 0; nf < 4; nf++) {
        int n = n0 + wn * 32 + nf * 8 + cq;
        float b0 = __ldg(&bias[n]), b1 = __ldg(&bias[n + 1]);
        float s0 = __ldg(&bng[n]) * rsqrtf(__ldg(&bnv[n]) + 1e-3f);
        float s1 = __ldg(&bng[n + 1]) * rsqrtf(__ldg(&bnv[n + 1]) + 1e-3f);
        mul0[nf] = s0; mul1[nf] = s1;
        add0[nf] = s0 * (b0 - __ldg(&bnm[n])) + __ldg(&bnb[n]);
        add1[nf] = s1 * (b1 - __ldg(&bnm[n + 1])) + __ldg(&bnb[n + 1]);
    }
#pragma unroll
    for (int mf = 0; mf < 4; mf++) {
#pragma unroll
        for (int half = 0; half < 2; half++) {
            int m = wm * 64 + mf * 16 + r0 + half * 8;
#pragma unroll
            for (int nf = 0; nf < 4; nf++) {
                float v0 = fmaxf(fmaf(cacc[mf][nf][2 * half + 0], mul0[nf], add0[nf]), 0.f);
                float v1 = fmaxf(fmaf(cacc[mf][nf][2 * half + 1], mul1[nf], add1[nf]), 0.f);
                int nc = n0 + wn * 32 + nf * 8 + cq;
                size_t off = (size_t)bz * XPD_ + (size_t)(t0 + m + 2) * D_ + nc;
                *(uint32_t*)(Cp + off) = (uint32_t)f2h(v0) | ((uint32_t)f2h(v1) << 16);
            }
        }
    }
}

// ---------------- fused fw+bw LSTM-pre GEMM (colp-permuted output) ----------------
__global__ __launch_bounds__(256, 2) void mma_gemm_pre(
    const uint16_t* __restrict__ Ap,
    const uint16_t* __restrict__ Bhf, const uint16_t* __restrict__ Blf,
    const uint16_t* __restrict__ Bhb, const uint16_t* __restrict__ Blb,
    const float* __restrict__ bias_f, const float* __restrict__ bias_b,
    float* __restrict__ pre_f, float* __restrict__ pre_b)
{
    extern __shared__ char smraw[];
    const uint32_t sbase = smem_u32(smraw);
    const int KKtot = D_;

    const int tid = threadIdx.x;
    const int wid = tid >> 5, lane = tid & 31;
    const int bz = blockIdx.z;
    const int t0 = blockIdx.y * BM;
    const int fw = (blockIdx.x < 8);
    const int n0 = (blockIdx.x & 7) * BN;
    const int wm = wid & 1;
    const int wn = wid >> 1;

    const uint16_t* Bh = fw ? Bhf : Bhb;
    const uint16_t* Bl = fw ? Blf : Blb;
    const float* bias = fw ? bias_f : bias_b;
    float* Cf = fw ? pre_f : pre_b;

    const uint32_t a_off = (uint32_t)((wm * 64 + (lane & 15)) * ROWB + (lane >> 4) * 16);
    const uint32_t b_off = (uint32_t)((wn * 32 + (lane & 7) + ((lane >> 4) << 3)) * ROWB
                                      + ((lane >> 3) & 1) * 16);

    const uint16_t* Ab = Ap + (size_t)bz * XPD_;
    const int NCH = KKtot / KC;

    float cacc[4][4][4];
#pragma unroll
    for (int i = 0; i < 4; i++)
#pragma unroll
        for (int j = 0; j < 4; j++)
#pragma unroll
            for (int q = 0; q < 4; q++) cacc[i][j][q] = 0.f;

    auto issue = [&](int cc) {
        const int st = cc % NSTG;
        const int kk0 = cc * KC;
        const uint32_t sb = sbase + st * STAGEB;
#pragma unroll
        for (int half = 0; half < 2; half++) {
            const int s = tid + half * 256;
            const int row = s >> 2, seg = s & 3;
            const uint32_t doff = (uint32_t)(row * ROWB + seg * 16);
            const size_t aoff = (size_t)(t0 + row) * D_ + kk0 + seg * 8;
            const size_t boff = (size_t)(n0 + row) * KKtot + kk0 + seg * 8;
            CP16(sb + doff,             Ab + aoff);
            CP16(sb + TILEB + doff,     Bh + boff);
            CP16(sb + 2 * TILEB + doff, Bl + boff);
        }
        CP_COMMIT();
    };

    auto compute = [&](int st) {
        const uint32_t SB = sbase + st * STAGEB;
#pragma unroll
        for (int k16 = 0; k16 < 2; k16++) {
            const uint32_t kof = k16 * 32;
            uint32_t bh[4][2], bl[4][2];
#pragma unroll
            for (int nfp = 0; nfp < 2; nfp++) {
                uint32_t bd = SB + TILEB + b_off + nfp * (16 * ROWB) + kof;
                LDM_X4(bh[2 * nfp][0], bh[2 * nfp][1], bh[2 * nfp + 1][0], bh[2 * nfp + 1][1], bd);
                LDM_X4(bl[2 * nfp][0], bl[2 * nfp][1], bl[2 * nfp + 1][0], bl[2 * nfp + 1][1], bd + TILEB);
            }
#pragma unroll
            for (int mf = 0; mf < 4; mf++) {
                uint32_t af[4];
                uint32_t ad = SB + a_off + mf * (16 * ROWB) + kof;
                LDM_X4(af[0], af[1], af[2], af[3], ad);
#pragma unroll
                for (int nf = 0; nf < 4; nf++) {
                    mma_f16(cacc[mf][nf], af, bh[nf]);
                    mma_f16(cacc[mf][nf], af, bl[nf]);
                }
            }
        }
    };

    issue(0);
    issue(1);
    for (int cc = 0; cc < NCH; cc++) {
        CP_WAIT(1);
        __syncthreads();
        if (cc + 2 < NCH) issue(cc + 2);
        else CP_COMMIT();
        compute(cc % NSTG);
    }

    const int r0 = lane >> 2;
    const int cq = (lane & 3) * 2;
    float add0[4], add1[4];
#pragma unroll
    for (int nf = 0; nf < 4; nf++) {
        int n = n0 + wn * 32 + nf * 8 + cq;
        add0[nf] = __ldg(&bias[n]);
        add1[nf] = __ldg(&bias[n + 1]);
    }
#pragma unroll
    for (int mf = 0; mf < 4; mf++) {
#pragma unroll
        for (int half = 0; half < 2; half++) {
            int m = wm * 64 + mf * 16 + r0 + half * 8;
            int t = t0 + m;
            size_t rowoff = fw ? ((size_t)t * B_ + bz) * G4_
                               : ((size_t)(T_ - 1 - t) * B_ + bz) * G4_;
#pragma unroll
            for (int nf = 0; nf < 4; nf++) {
                int nc = n0 + wn * 32 + nf * 8 + cq;       // gate-major col
                int u = nc & 255, g = nc >> 8;
                float v0 = cacc[mf][nf][2 * half + 0] + add0[nf];
                float v1 = cacc[mf][nf][2 * half + 1] + add1[nf];
                Cf[rowoff + 4 * u + g] = v0;               // colp = 4u+g
                Cf[rowoff + 4 * (u + 1) + g] = v1;
            }
        }
    }
}

// ---------------- tensor-core bi-LSTM recurrence ----------------
// 32 CTAs: dir = bx>>4, cta = bx&15. Each CTA: M=64 batches x N=64 gate-cols
// (= 16 units), K=256. Wr slice persistent in smem; h exchanged via global
// fp16 hi/lo buffers; barrier = per-dir atomic counter over 16 CTAs.
__global__ __launch_bounds__(256) void lstm_tc_kernel(
    const float* __restrict__ pre_f, const float* __restrict__ pre_b,
    float* __restrict__ out)
{
    extern __shared__ char smraw[];
    const uint32_t sbase = smem_u32(smraw);
    // H tiles: (c*2+p)*LTILE  (c=0..7, p=hi/lo)   [0, 81920)
    // W tiles: 81920 + (c*2+p)*LTILE              [81920, 163840)

    const int bx = blockIdx.x;
    const int dir = bx >> 4;
    const int cta = bx & 15;
    const float* pre = dir ? pre_b : pre_f;
    unsigned* bar = &g_bar[dir];

    const int tid = threadIdx.x;
    const int wid = tid >> 5, lane = tid & 31;
    const int wm = wid & 1;          // batch half: rows wm*32..+32
    const int wn = wid >> 1;         // col group: 16 cols each (4 units)
    const int gid = lane >> 2;
    const int lpair = lane & 3;
    const int isodd = lane & 1;

    // preload W tiles (persistent across all steps)
    {
        const uint16_t* wh = g_wrh + (size_t)dir * 1024 * 256 + (size_t)cta * 64 * 256;
        const uint16_t* wl = g_wrl + (size_t)dir * 1024 * 256 + (size_t)cta * 64 * 256;
        for (int s = tid; s < 4096; s += 256) {
            int tile = s >> 8, row = (s >> 2) & 63, seg = s & 3;
            int p = tile & 1, c = tile >> 1;
            const uint16_t* src = (p ? wl : wh) + row * 256 + c * 32 + seg * 8;
            uint4 v = *(const uint4*)src;
            *(uint4*)(smraw + 81920 + (c * 2 + p) * LTILE + row * ROWB + seg * 16) = v;
        }
    }

    const uint32_t a_off = (uint32_t)((wm * 32 + (lane & 15)) * ROWB + (lane >> 4) * 16);
    const uint32_t b_off = (uint32_t)(81920 + (wn * 16 + (lane & 7) + ((lane >> 4) << 3)) * ROWB
                                      + ((lane >> 3) & 1) * 16);

    float cst[2][2] = {{0.f, 0.f}, {0.f, 0.f}};   // c-state per (mf, n8)
    __syncthreads();

    for (int t = 0; t < T_; t++) {
        // p prefetch: float4 of 4 gates for each owned (b,u)
        float4 pv[2][2];
#pragma unroll
        for (int mf = 0; mf < 2; mf++)
#pragma unroll
            for (int n8 = 0; n8 < 2; n8++) {
                int b = wm * 32 + mf * 16 + gid + (isodd ? 8 : 0);
                int u = cta * 16 + wn * 4 + n8 * 2 + (lpair >> 1);
                pv[mf][n8] = __ldg((const float4*)(pre + ((size_t)t * B_ + b) * G4_ + 4 * u));
            }

        // stage h hi/lo into H tiles (16 independent ldcg.128 per thread)
        const int slot = (t + 1) & 1;
        const uint16_t* hhr = &g_hh[dir][slot][0];
        const uint16_t* hlr = &g_hl[dir][slot][0];
#pragma unroll
        for (int j = 0; j < 16; j++) {
            int s = tid + j * 256;
            int tile = s >> 8, row = (s >> 2) & 63, seg = s & 3;
            int p = tile & 1, c = tile >> 1;
            const uint16_t* src = (p ? hlr : hhr) + row * 256 + c * 32 + seg * 8;
            uint4 v = __ldcg((const uint4*)src);
            *(uint4*)(smraw + (c * 2 + p) * LTILE + row * ROWB + seg * 16) = v;
        }
        __syncthreads();

        float acc[2][2][4];
#pragma unroll
        for (int i = 0; i < 2; i++)
#pragma unroll
            for (int j = 0; j < 2; j++)
#pragma unroll
                for (int q = 0; q < 4; q++) acc[i][j][q] = 0.f;

#pragma unroll
        for (int c = 0; c < 8; c++) {
#pragma unroll
            for (int k16 = 0; k16 < 2; k16++) {
                const uint32_t kof = k16 * 32;
                uint32_t bh[2][2], bl[2][2];
                uint32_t bdh = sbase + b_off + (c * 2 + 0) * LTILE + kof;
                uint32_t bdl = sbase + b_off + (c * 2 + 1) * LTILE + kof;
                LDM_X4(bh[0][0], bh[0][1], bh[1][0], bh[1][1], bdh);
                LDM_X4(bl[0][0], bl[0][1], bl[1][0], bl[1][1], bdl);
#pragma unroll
                for (int mf = 0; mf < 2; mf++) {
                    uint32_t ah[4], al[4];
                    uint32_t adh = sbase + (c * 2 + 0) * LTILE + a_off + mf * (16 * ROWB) + kof;
                    uint32_t adl = sbase + (c * 2 + 1) * LTILE + a_off + mf * (16 * ROWB) + kof;
                    LDM_X4(ah[0], ah[1], ah[2], ah[3], adh);
                    LDM_X4(al[0], al[1], al[2], al[3], adl);
#pragma unroll
                    for (int n8 = 0; n8 < 2; n8++) {
                        mma_f16(acc[mf][n8], ah, bh[n8]);
                        mma_f16(acc[mf][n8], al, bh[n8]);
                        mma_f16(acc[mf][n8], ah, bl[n8]);
                    }
                }
            }
        }
        __syncthreads();   // H tiles free for next step after this

        // epilogue: gates, c-update, h writes
        uint16_t* hhw = &g_hh[dir][t & 1][0];
        uint16_t* hlw = &g_hl[dir][t & 1][0];
#pragma unroll
        for (int mf = 0; mf < 2; mf++) {
#pragma unroll
            for (int n8 = 0; n8 < 2; n8++) {
                float o0 = acc[mf][n8][0], o1 = acc[mf][n8][1];
                float o2 = acc[mf][n8][2], o3 = acc[mf][n8][3];
                float r0v = __shfl_xor_sync(0xFFFFFFFFu, o0, 1);
                float r1v = __shfl_xor_sync(0xFFFFFFFFu, o1, 1);
                float r2v = __shfl_xor_sync(0xFFFFFFFFu, o2, 1);
                float r3v = __shfl_xor_sync(0xFFFFFFFFu, o3, 1);
                float zi, zf, zg, zo;
                if (!isodd) { zi = o0;  zf = o1;  zg = r0v; zo = r1v; }   // row gid
                else        { zi = r2v; zf = r3v; zg = o2;  zo = o3;  }   // row gid+8
                float4 p4 = pv[mf][n8];
                zi += p4.x; zf += p4.y; zg += p4.z; zo += p4.w;
                float ig = 1.f / (1.f + __expf(-zi));
                float fg = 1.f / (1.f + __expf(-zf));
                float gg = tanhf(zg);
                float og = 1.f / (1.f + __expf(-zo));
                float cc = fg * cst[mf][n8] + ig * gg;
                cst[mf][n8] = cc;
                float h = og * tanhf(cc);

                int b = wm * 32 + mf * 16 + gid + (isodd ? 8 : 0);
                int u = cta * 16 + wn * 4 + n8 * 2 + (lpair >> 1);
                uint16_t hh16, hl16;
                split_h16(h, hh16, hl16);
                hhw[b * U_ + u] = hh16;
                hlw[b * U_ + u] = hl16;
                int tout = dir ? (T_ - 1 - t) : t;
                out[((size_t)b * T_ + tout) * (2 * U_) + dir * U_ + u] = h;
            }
        }

        __syncthreads();
        if (tid == 0) {
            __threadfence();
            atomicAdd(bar, 1u);
            unsigned target = (unsigned)(t + 1) * 16u;
            unsigned v;
            do {
                asm volatile("ld.global.acquire.gpu.u32 %0, [%1];" : "=r"(v) : "l"(bar));
            } while (v < target);
        }
        __syncthreads();
    }
}

// ---------------- launcher ----------------
extern "C" void kernel_launch(void* const* d_in, const int* in_sizes, int n_in,
                              void* d_out, int out_size)
{
    const float* inputs = (const float*)d_in[0];
    const float* convk  = (const float*)d_in[1];
    const float* convb  = (const float*)d_in[2];
    const float* bng    = (const float*)d_in[3];
    const float* bnb    = (const float*)d_in[4];
    const float* bnm    = (const float*)d_in[5];
    const float* bnv    = (const float*)d_in[6];
    const float* wk_f   = (const float*)d_in[7];
    const float* wr_f   = (const float*)d_in[8];
    const float* bi_f   = (const float*)d_in[9];
    const float* wk_b   = (const float*)d_in[10];
    const float* wr_b   = (const float*)d_in[11];
    const float* bi_b   = (const float*)d_in[12];
    float* out = (float*)d_out;

    uint16_t *x0, *x1, *wch, *wcl, *wlh, *wll;
    float *pre_f, *pre_b;
    cudaGetSymbolAddress((void**)&x0, g_x0);
    cudaGetSymbolAddress((void**)&x1, g_x1);
    cudaGetSymbolAddress((void**)&wch, g_wch);
    cudaGetSymbolAddress((void**)&wcl, g_wcl);
    cudaGetSymbolAddress((void**)&wlh, g_wlh);
    cudaGetSymbolAddress((void**)&wll, g_wll);
    cudaGetSymbolAddress((void**)&pre_f, g_pre_f);
    cudaGetSymbolAddress((void**)&pre_b, g_pre_b);

    cudaFuncSetAttribute(mma_gemm_conv, cudaFuncAttributeMaxDynamicSharedMemorySize, GSMEM);
    cudaFuncSetAttribute(mma_gemm_pre,  cudaFuncAttributeMaxDynamicSharedMemorySize, GSMEM);
    cudaFuncSetAttribute(lstm_tc_kernel, cudaFuncAttributeMaxDynamicSharedMemorySize, LSMEM);

    prep_kernel<<<8192, 256>>>(inputs, convk, wk_f, wk_b, wr_f, wr_b);

    const size_t wcs = (size_t)512 * 2560;
    dim3 gc(D_ / BN, T_ / BM, B_);
    mma_gemm_conv<<<gc, 256, GSMEM>>>(x0, wch + 0 * wcs, wcl + 0 * wcs,
                                      convb + 0 * D_, bng + 0 * D_, bnb + 0 * D_,
                                      bnm + 0 * D_, bnv + 0 * D_, x1);
    mma_gemm_conv<<<gc, 256, GSMEM>>>(x1, wch + 1 * wcs, wcl + 1 * wcs,
                                      convb + 1 * D_, bng + 1 * D_, bnb + 1 * D_,
                                      bnm + 1 * D_, bnv + 1 * D_, x0);
    mma_gemm_conv<<<gc, 256, GSMEM>>>(x0, wch + 2 * wcs, wcl + 2 * wcs,
                                      convb + 2 * D_, bng + 2 * D_, bnb + 2 * D_,
                                      bnm + 2 * D_, bnv + 2 * D_, x1);

    const size_t wls = (size_t)1024 * 512;
    dim3 gl(16, T_ / BM, B_);
    mma_gemm_pre<<<gl, 256, GSMEM>>>(x1 + 2 * D_,
                                     wlh + 0 * wls, wll + 0 * wls,
                                     wlh + 1 * wls, wll + 1 * wls,
                                     bi_f, bi_b, pre_f, pre_b);

    lstm_tc_kernel<<<32, 256, LSMEM>>>(pre_f, pre_b, out);
}

// round 14
// speedup vs baseline: 1.3861x; 1.0495x over previous
#include <cuda_runtime.h>
#include <cuda_fp16.h>
#include <cstdint>
#include <math.h>

#define B_    64
#define T_    1024
#define D_    512
#define KTAP  5
#define U_    256
#define G4_   1024
#define TP_   (T_ + 4)
#define XPD_  (TP_ * D_)

#define BM    128
#define BN    128
#define KC    32
#define ROWB  80
#define TILEB (128 * ROWB)
#define STAGEB (3 * TILEB)
#define NSTG  3
#define GSMEM (NSTG * STAGEB)

// lstm tc kernel tiles: 64 rows x 80B = 5120 B
#define LTILE 5120
#define LOUTOFF (32 * LTILE)         // out-stage region after 16 H + 16 W tiles
#define LSMEM (LOUTOFF + 4096)       // + 1024 floats for coalesced out staging

// ---------------- scratch ----------------
__device__ uint16_t g_x0[(size_t)B_ * XPD_];
__device__ uint16_t g_x1[(size_t)B_ * XPD_];
__device__ uint16_t g_wch[(size_t)3 * 512 * 2560];
__device__ uint16_t g_wcl[(size_t)3 * 512 * 2560];
__device__ uint16_t g_wlh[(size_t)2 * 1024 * 512];
__device__ uint16_t g_wll[(size_t)2 * 1024 * 512];
__device__ uint16_t g_wrh[(size_t)2 * 1024 * 256];  // recurrent W, [dir][colp][k]
__device__ uint16_t g_wrl[(size_t)2 * 1024 * 256];
__device__ float    g_pre_f[(size_t)T_ * B_ * G4_]; // colp-permuted [t][b][4u+g]
__device__ float    g_pre_b[(size_t)T_ * B_ * G4_];
__device__ uint16_t g_hh[2][2][B_ * U_];            // h fp16 hi [dir][slot][b*256+u]
__device__ uint16_t g_hl[2][2][B_ * U_];
__device__ unsigned g_bar[2];

// ---------------- helpers ----------------
__device__ __forceinline__ uint32_t smem_u32(const void* p) {
    uint32_t a;
    asm("{ .reg .u64 t; cvta.to.shared.u64 t, %1; cvt.u32.u64 %0, t; }" : "=r"(a) : "l"(p));
    return a;
}
__device__ __forceinline__ uint16_t f2h(float v) {
    return __half_as_ushort(__float2half(v));
}
__device__ __forceinline__ void split_h16(float v, uint16_t& h, uint16_t& l) {
    __half hh = __float2half(v);
    float hf = __half2float(hh);
    h = __half_as_ushort(hh);
    l = __half_as_ushort(__float2half(v - hf));
}
#define CP16(dst, src) \
    asm volatile("cp.async.cg.shared.global [%0], [%1], 16;" :: "r"(dst), "l"(src))
#define CP_COMMIT() asm volatile("cp.async.commit_group;" ::: "memory")
#define CP_WAIT(N)  asm volatile("cp.async.wait_group %0;" :: "n"(N) : "memory")
#define LDM_X4(R0, R1, R2, R3, ADDR)                                            \
    asm volatile("ldmatrix.sync.aligned.m8n8.x4.shared.b16 {%0,%1,%2,%3}, [%4];"\
        : "=r"(R0), "=r"(R1), "=r"(R2), "=r"(R3) : "r"(ADDR))
__device__ __forceinline__ void mma_f16(float* c, const uint32_t* a, const uint32_t* b) {
    asm volatile(
        "mma.sync.aligned.m16n8k16.row.col.f32.f16.f16.f32 "
        "{%0,%1,%2,%3}, {%4,%5,%6,%7}, {%8,%9}, {%0,%1,%2,%3};"
        : "+f"(c[0]), "+f"(c[1]), "+f"(c[2]), "+f"(c[3])
        : "r"(a[0]), "r"(a[1]), "r"(a[2]), "r"(a[3]), "r"(b[0]), "r"(b[1]));
}

// ---------------- fused prep ----------------
__global__ void prep_kernel(const float* __restrict__ in,
                            const float* __restrict__ convk,
                            const float* __restrict__ wkf,
                            const float* __restrict__ wkb,
                            const float* __restrict__ wrf,
                            const float* __restrict__ wrb) {
    const size_t stride = (size_t)gridDim.x * blockDim.x;
    const size_t tid0 = (size_t)blockIdx.x * blockDim.x + threadIdx.x;

    for (size_t idx = tid0; idx < (size_t)B_ * 4 * D_; idx += stride) {
        int b = (int)(idx / (4 * D_));
        int r = (int)((idx / D_) & 3);
        int d = (int)(idx % D_);
        int row = (r < 2) ? r : (TP_ - 4 + r);
        size_t o = (size_t)b * XPD_ + (size_t)row * D_ + d;
        g_x0[o] = 0; g_x1[o] = 0;
    }
    for (size_t idx = tid0; idx < (size_t)2 * 2 * B_ * U_ / 2; idx += stride) {
        ((uint32_t*)g_hh)[idx] = 0u;
        ((uint32_t*)g_hl)[idx] = 0u;
    }
    if (tid0 < 2) g_bar[tid0] = 0u;

    for (size_t idx = tid0; idx < (size_t)B_ * T_ * D_; idx += stride) {
        size_t b = idx / ((size_t)T_ * D_);
        size_t r = idx % ((size_t)T_ * D_);
        size_t t = r / D_, d = r % D_;
        g_x0[b * XPD_ + (t + 2) * D_ + d] = f2h(in[idx]);
    }

    const size_t CONVN = (size_t)3 * 512 * 2560;
    const size_t LSTMN = (size_t)1024 * 512;
    for (size_t idx = tid0; idx < CONVN + 2 * LSTMN; idx += stride) {
        uint16_t h, l;
        if (idx < CONVN) {
            size_t i = idx / ((size_t)512 * 2560);
            size_t r = idx % ((size_t)512 * 2560);
            size_t n = r / 2560, kk = r % 2560;
            size_t tap = kk >> 9, din = kk & 511;
            split_h16(convk[(((i * KTAP + tap) * D_) + din) * D_ + n], h, l);
            g_wch[idx] = h; g_wcl[idx] = l;
        } else if (idx < CONVN + LSTMN) {
            size_t j = idx - CONVN;
            size_t n = j >> 9, d = j & 511;
            split_h16(wkf[d * G4_ + n], h, l);
            g_wlh[j] = h; g_wll[j] = l;
        } else {
            size_t j = idx - CONVN - LSTMN;
            size_t n = j >> 9, d = j & 511;
            split_h16(wkb[d * G4_ + n], h, l);
            g_wlh[LSTMN + j] = h; g_wll[LSTMN + j] = l;
        }
    }

    const size_t WRN = (size_t)2 * 1024 * 256;
    for (size_t idx = tid0; idx < WRN; idx += stride) {
        size_t dir = idx >> 18;
        size_t r = idx & 262143;
        size_t colp = r >> 8, k = r & 255;
        size_t u = colp >> 2, g = colp & 3;
        const float* wr = dir ? wrb : wrf;
        uint16_t h, l;
        split_h16(wr[k * G4_ + g * U_ + u], h, l);
        g_wrh[idx] = h; g_wrl[idx] = l;
    }
}

// ---------------- fp16 2-term warp-MMA conv GEMM ----------------
__global__ __launch_bounds__(256, 2) void mma_gemm_conv(
    const uint16_t* __restrict__ Ap,
    const uint16_t* __restrict__ Bh, const uint16_t* __restrict__ Bl,
    const float* __restrict__ bias,
    const float* __restrict__ bng, const float* __restrict__ bnb,
    const float* __restrict__ bnm, const float* __restrict__ bnv,
    uint16_t* __restrict__ Cp)
{
    extern __shared__ char smraw[];
    const uint32_t sbase = smem_u32(smraw);
    const int KKtot = KTAP * D_;

    const int tid = threadIdx.x;
    const int wid = tid >> 5, lane = tid & 31;
    const int bz = blockIdx.z;
    const int t0 = blockIdx.y * BM;
    const int n0 = blockIdx.x * BN;
    const int wm = wid & 1;
    const int wn = wid >> 1;

    const uint32_t a_off = (uint32_t)((wm * 64 + (lane & 15)) * ROWB + (lane >> 4) * 16);
    const uint32_t b_off = (uint32_t)((wn * 32 + (lane & 7) + ((lane >> 4) << 3)) * ROWB
                                      + ((lane >> 3) & 1) * 16);

    const uint16_t* Ab = Ap + (size_t)bz * XPD_;
    const int NCH = KKtot / KC;

    float cacc[4][4][4];
#pragma unroll
    for (int i = 0; i < 4; i++)
#pragma unroll
        for (int j = 0; j < 4; j++)
#pragma unroll
            for (int q = 0; q < 4; q++) cacc[i][j][q] = 0.f;

    auto issue = [&](int cc) {
        const int st = cc % NSTG;
        const int kk0 = cc * KC;
        const int tap = kk0 >> 9;
        const int d0 = kk0 & 511;
        const uint32_t sb = sbase + st * STAGEB;
#pragma unroll
        for (int half = 0; half < 2; half++) {
            const int s = tid + half * 256;
            const int row = s >> 2, seg = s & 3;
            const uint32_t doff = (uint32_t)(row * ROWB + seg * 16);
            const size_t aoff = (size_t)(t0 + row + tap) * D_ + d0 + seg * 8;
            const size_t boff = (size_t)(n0 + row) * KKtot + kk0 + seg * 8;
            CP16(sb + doff,             Ab + aoff);
            CP16(sb + TILEB + doff,     Bh + boff);
            CP16(sb + 2 * TILEB + doff, Bl + boff);
        }
        CP_COMMIT();
    };

    auto compute = [&](int st) {
        const uint32_t SB = sbase + st * STAGEB;
#pragma unroll
        for (int k16 = 0; k16 < 2; k16++) {
            const uint32_t kof = k16 * 32;
            uint32_t bh[4][2], bl[4][2];
#pragma unroll
            for (int nfp = 0; nfp < 2; nfp++) {
                uint32_t bd = SB + TILEB + b_off + nfp * (16 * ROWB) + kof;
                LDM_X4(bh[2 * nfp][0], bh[2 * nfp][1], bh[2 * nfp + 1][0], bh[2 * nfp + 1][1], bd);
                LDM_X4(bl[2 * nfp][0], bl[2 * nfp][1], bl[2 * nfp + 1][0], bl[2 * nfp + 1][1], bd + TILEB);
            }
#pragma unroll
            for (int mf = 0; mf < 4; mf++) {
                uint32_t af[4];
                uint32_t ad = SB + a_off + mf * (16 * ROWB) + kof;
                LDM_X4(af[0], af[1], af[2], af[3], ad);
#pragma unroll
                for (int nf = 0; nf < 4; nf++) {
                    mma_f16(cacc[mf][nf], af, bh[nf]);
                    mma_f16(cacc[mf][nf], af, bl[nf]);
                }
            }
        }
    };

    issue(0);
    issue(1);
    for (int cc = 0; cc < NCH; cc++) {
        CP_WAIT(1);
        __syncthreads();
        if (cc + 2 < NCH) issue(cc + 2);
        else CP_COMMIT();
        compute(cc % NSTG);
    }

    const int r0 = lane >> 2;
    const int cq = (lane & 3) * 2;
    float mul0[4], mul1[4], add0[4], add1[4];
#pragma unroll
    for (int nf = 0; nf < 4; nf++) {
        int n = n0 + wn * 32 + nf * 8 + cq;
        float b0 = __ldg(&bias[n]), b1 = __ldg(&bias[n + 1]);
        float s0 = __ldg(&bng[n]) * rsqrtf(__ldg(&bnv[n]) + 1e-3f);
        float s1 = __ldg(&bng[n + 1]) * rsqrtf(__ldg(&bnv[n + 1]) + 1e-3f);
        mul0[nf] = s0; mul1[nf] = s1;
        add0[nf] = s0 * (b0 - __ldg(&bnm[n])) + __ldg(&bnb[n]);
        add1[nf] = s1 * (b1 - __ldg(&bnm[n + 1])) + __ldg(&bnb[n + 1]);
    }
#pragma unroll
    for (int mf = 0; mf < 4; mf++) {
#pragma unroll
        for (int half = 0; half < 2; half++) {
            int m = wm * 64 + mf * 16 + r0 + half * 8;
#pragma unroll
            for (int nf = 0; nf < 4; nf++) {
                float v0 = fmaxf(fmaf(cacc[mf][nf][2 * half + 0], mul0[nf], add0[nf]), 0.f);
                float v1 = fmaxf(fmaf(cacc[mf][nf][2 * half + 1], mul1[nf], add1[nf]), 0.f);
                int nc = n0 + wn * 32 + nf * 8 + cq;
                size_t off = (size_t)bz * XPD_ + (size_t)(t0 + m + 2) * D_ + nc;
                *(uint32_t*)(Cp + off) = (uint32_t)f2h(v0) | ((uint32_t)f2h(v1) << 16);
            }
        }
    }
}

// ---------------- fused fw+bw LSTM-pre GEMM (colp-permuted output) ----------------
__global__ __launch_bounds__(256, 2) void mma_gemm_pre(
    const uint16_t* __restrict__ Ap,
    const uint16_t* __restrict__ Bhf, const uint16_t* __restrict__ Blf,
    const uint16_t* __restrict__ Bhb, const uint16_t* __restrict__ Blb,
    const float* __restrict__ bias_f, const float* __restrict__ bias_b,
    float* __restrict__ pre_f, float* __restrict__ pre_b)
{
    extern __shared__ char smraw[];
    const uint32_t sbase = smem_u32(smraw);
    const int KKtot = D_;

    const int tid = threadIdx.x;
    const int wid = tid >> 5, lane = tid & 31;
    const int bz = blockIdx.z;
    const int t0 = blockIdx.y * BM;
    const int fw = (blockIdx.x < 8);
    const int n0 = (blockIdx.x & 7) * BN;
    const int wm = wid & 1;
    const int wn = wid >> 1;

    const uint16_t* Bh = fw ? Bhf : Bhb;
    const uint16_t* Bl = fw ? Blf : Blb;
    const float* bias = fw ? bias_f : bias_b;
    float* Cf = fw ? pre_f : pre_b;

    const uint32_t a_off = (uint32_t)((wm * 64 + (lane & 15)) * ROWB + (lane >> 4) * 16);
    const uint32_t b_off = (uint32_t)((wn * 32 + (lane & 7) + ((lane >> 4) << 3)) * ROWB
                                      + ((lane >> 3) & 1) * 16);

    const uint16_t* Ab = Ap + (size_t)bz * XPD_;
    const int NCH = KKtot / KC;

    float cacc[4][4][4];
#pragma unroll
    for (int i = 0; i < 4; i++)
#pragma unroll
        for (int j = 0; j < 4; j++)
#pragma unroll
            for (int q = 0; q < 4; q++) cacc[i][j][q] = 0.f;

    auto issue = [&](int cc) {
        const int st = cc % NSTG;
        const int kk0 = cc * KC;
        const uint32_t sb = sbase + st * STAGEB;
#pragma unroll
        for (int half = 0; half < 2; half++) {
            const int s = tid + half * 256;
            const int row = s >> 2, seg = s & 3;
            const uint32_t doff = (uint32_t)(row * ROWB + seg * 16);
            const size_t aoff = (size_t)(t0 + row) * D_ + kk0 + seg * 8;
            const size_t boff = (size_t)(n0 + row) * KKtot + kk0 + seg * 8;
            CP16(sb + doff,             Ab + aoff);
            CP16(sb + TILEB + doff,     Bh + boff);
            CP16(sb + 2 * TILEB + doff, Bl + boff);
        }
        CP_COMMIT();
    };

    auto compute = [&](int st) {
        const uint32_t SB = sbase + st * STAGEB;
#pragma unroll
        for (int k16 = 0; k16 < 2; k16++) {
            const uint32_t kof = k16 * 32;
            uint32_t bh[4][2], bl[4][2];
#pragma unroll
            for (int nfp = 0; nfp < 2; nfp++) {
                uint32_t bd = SB + TILEB + b_off + nfp * (16 * ROWB) + kof;
                LDM_X4(bh[2 * nfp][0], bh[2 * nfp][1], bh[2 * nfp + 1][0], bh[2 * nfp + 1][1], bd);
                LDM_X4(bl[2 * nfp][0], bl[2 * nfp][1], bl[2 * nfp + 1][0], bl[2 * nfp + 1][1], bd + TILEB);
            }
#pragma unroll
            for (int mf = 0; mf < 4; mf++) {
                uint32_t af[4];
                uint32_t ad = SB + a_off + mf * (16 * ROWB) + kof;
                LDM_X4(af[0], af[1], af[2], af[3], ad);
#pragma unroll
                for (int nf = 0; nf < 4; nf++) {
                    mma_f16(cacc[mf][nf], af, bh[nf]);
                    mma_f16(cacc[mf][nf], af, bl[nf]);
                }
            }
        }
    };

    issue(0);
    issue(1);
    for (int cc = 0; cc < NCH; cc++) {
        CP_WAIT(1);
        __syncthreads();
        if (cc + 2 < NCH) issue(cc + 2);
        else CP_COMMIT();
        compute(cc % NSTG);
    }

    const int r0 = lane >> 2;
    const int cq = (lane & 3) * 2;
    float add0[4], add1[4];
#pragma unroll
    for (int nf = 0; nf < 4; nf++) {
        int n = n0 + wn * 32 + nf * 8 + cq;
        add0[nf] = __ldg(&bias[n]);
        add1[nf] = __ldg(&bias[n + 1]);
    }
#pragma unroll
    for (int mf = 0; mf < 4; mf++) {
#pragma unroll
        for (int half = 0; half < 2; half++) {
            int m = wm * 64 + mf * 16 + r0 + half * 8;
            int t = t0 + m;
            size_t rowoff = fw ? ((size_t)t * B_ + bz) * G4_
                               : ((size_t)(T_ - 1 - t) * B_ + bz) * G4_;
#pragma unroll
            for (int nf = 0; nf < 4; nf++) {
                int nc = n0 + wn * 32 + nf * 8 + cq;
                int u = nc & 255, g = nc >> 8;
                float v0 = cacc[mf][nf][2 * half + 0] + add0[nf];
                float v1 = cacc[mf][nf][2 * half + 1] + add1[nf];
                Cf[rowoff + 4 * u + g] = v0;
                Cf[rowoff + 4 * (u + 1) + g] = v1;
            }
        }
    }
}

// ---------------- tensor-core bi-LSTM recurrence (pipelined staging) ----------------
__global__ __launch_bounds__(256) void lstm_tc_kernel(
    const float* __restrict__ pre_f, const float* __restrict__ pre_b,
    float* __restrict__ out)
{
    extern __shared__ char smraw[];
    const uint32_t sbase = smem_u32(smraw);
    float* sOut = (float*)(smraw + LOUTOFF);   // [64][16]

    const int bx = blockIdx.x;
    const int dir = bx >> 4;
    const int cta = bx & 15;
    const float* pre = dir ? pre_b : pre_f;
    unsigned* bar = &g_bar[dir];

    const int tid = threadIdx.x;
    const int wid = tid >> 5, lane = tid & 31;
    const int wm = wid & 1;
    const int wn = wid >> 1;
    const int gid = lane >> 2;
    const int lpair = lane & 3;
    const int isodd = lane & 1;

    // preload W tiles (persistent)
    {
        const uint16_t* wh = g_wrh + (size_t)dir * 1024 * 256 + (size_t)cta * 64 * 256;
        const uint16_t* wl = g_wrl + (size_t)dir * 1024 * 256 + (size_t)cta * 64 * 256;
        for (int s = tid; s < 4096; s += 256) {
            int tile = s >> 8, row = (s >> 2) & 63, seg = s & 3;
            int p = tile & 1, c = tile >> 1;
            const uint16_t* src = (p ? wl : wh) + row * 256 + c * 32 + seg * 8;
            uint4 v = *(const uint4*)src;
            *(uint4*)(smraw + 81920 + (c * 2 + p) * LTILE + row * ROWB + seg * 16) = v;
        }
    }

    const uint32_t a_off = (uint32_t)((wm * 32 + (lane & 15)) * ROWB + (lane >> 4) * 16);
    const uint32_t b_off = (uint32_t)(81920 + (wn * 16 + (lane & 7) + ((lane >> 4) << 3)) * ROWB
                                      + ((lane >> 3) & 1) * 16);

    float cst[2][2] = {{0.f, 0.f}, {0.f, 0.f}};
    __syncthreads();

    for (int t = 0; t < T_; t++) {
        // p prefetch
        float4 pv[2][2];
#pragma unroll
        for (int mf = 0; mf < 2; mf++)
#pragma unroll
            for (int n8 = 0; n8 < 2; n8++) {
                int b = wm * 32 + mf * 16 + gid + (isodd ? 8 : 0);
                int u = cta * 16 + wn * 4 + n8 * 2 + (lpair >> 1);
                pv[mf][n8] = __ldg((const float4*)(pre + ((size_t)t * B_ + b) * G4_ + 4 * u));
            }

        // cp.async staging in 2 half-groups: tiles 0..7 (c=0..3), tiles 8..15 (c=4..7)
        const int slot = (t + 1) & 1;
        const uint16_t* hhr = &g_hh[dir][slot][0];
        const uint16_t* hlr = &g_hl[dir][slot][0];
#pragma unroll
        for (int half = 0; half < 2; half++) {
#pragma unroll
            for (int j = 0; j < 8; j++) {
                int s = tid + (half * 8 + j) * 256;
                int tile = s >> 8, row = (s >> 2) & 63, seg = s & 3;
                int p = tile & 1, c = tile >> 1;
                const uint16_t* src = (p ? hlr : hhr) + row * 256 + c * 32 + seg * 8;
                CP16(sbase + (c * 2 + p) * LTILE + (uint32_t)(row * ROWB + seg * 16), src);
            }
            CP_COMMIT();
        }

        float acc[2][2][4];
#pragma unroll
        for (int i = 0; i < 2; i++)
#pragma unroll
            for (int j = 0; j < 2; j++)
#pragma unroll
                for (int q = 0; q < 4; q++) acc[i][j][q] = 0.f;

        // first half: wait group A, compute c=0..3 (group B lands underneath)
        CP_WAIT(1);
        __syncthreads();
#pragma unroll
        for (int c = 0; c < 4; c++) {
#pragma unroll
            for (int k16 = 0; k16 < 2; k16++) {
                const uint32_t kof = k16 * 32;
                uint32_t bh[2][2], bl[2][2];
                LDM_X4(bh[0][0], bh[0][1], bh[1][0], bh[1][1],
                       sbase + b_off + (c * 2 + 0) * LTILE + kof);
                LDM_X4(bl[0][0], bl[0][1], bl[1][0], bl[1][1],
                       sbase + b_off + (c * 2 + 1) * LTILE + kof);
#pragma unroll
                for (int mf = 0; mf < 2; mf++) {
                    uint32_t ah[4], al[4];
                    LDM_X4(ah[0], ah[1], ah[2], ah[3],
                           sbase + (c * 2 + 0) * LTILE + a_off + mf * (16 * ROWB) + kof);
                    LDM_X4(al[0], al[1], al[2], al[3],
                           sbase + (c * 2 + 1) * LTILE + a_off + mf * (16 * ROWB) + kof);
#pragma unroll
                    for (int n8 = 0; n8 < 2; n8++) {
                        mma_f16(acc[mf][n8], ah, bh[n8]);
                        mma_f16(acc[mf][n8], al, bh[n8]);
                        mma_f16(acc[mf][n8], ah, bl[n8]);
                    }
                }
            }
        }
        // second half
        CP_WAIT(0);
        __syncthreads();
#pragma unroll
        for (int c = 4; c < 8; c++) {
#pragma unroll
            for (int k16 = 0; k16 < 2; k16++) {
                const uint32_t kof = k16 * 32;
                uint32_t bh[2][2], bl[2][2];
                LDM_X4(bh[0][0], bh[0][1], bh[1][0], bh[1][1],
                       sbase + b_off + (c * 2 + 0) * LTILE + kof);
                LDM_X4(bl[0][0], bl[0][1], bl[1][0], bl[1][1],
                       sbase + b_off + (c * 2 + 1) * LTILE + kof);
#pragma unroll
                for (int mf = 0; mf < 2; mf++) {
                    uint32_t ah[4], al[4];
                    LDM_X4(ah[0], ah[1], ah[2], ah[3],
                           sbase + (c * 2 + 0) * LTILE + a_off + mf * (16 * ROWB) + kof);
                    LDM_X4(al[0], al[1], al[2], al[3],
                           sbase + (c * 2 + 1) * LTILE + a_off + mf * (16 * ROWB) + kof);
#pragma unroll
                    for (int n8 = 0; n8 < 2; n8++) {
                        mma_f16(acc[mf][n8], ah, bh[n8]);
                        mma_f16(acc[mf][n8], al, bh[n8]);
                        mma_f16(acc[mf][n8], ah, bl[n8]);
                    }
                }
            }
        }
        __syncthreads();   // H tiles reusable next step

        // epilogue: gates, c-update, h global stores + smem out-stage
        uint16_t* hhw = &g_hh[dir][t & 1][0];
        uint16_t* hlw = &g_hl[dir][t & 1][0];
#pragma unroll
        for (int mf = 0; mf < 2; mf++) {
#pragma unroll
            for (int n8 = 0; n8 < 2; n8++) {
                float o0 = acc[mf][n8][0], o1 = acc[mf][n8][1];
                float o2 = acc[mf][n8][2], o3 = acc[mf][n8][3];
                float r0v = __shfl_xor_sync(0xFFFFFFFFu, o0, 1);
                float r1v = __shfl_xor_sync(0xFFFFFFFFu, o1, 1);
                float r2v = __shfl_xor_sync(0xFFFFFFFFu, o2, 1);
                float r3v = __shfl_xor_sync(0xFFFFFFFFu, o3, 1);
                float zi, zf, zg, zo;
                if (!isodd) { zi = o0;  zf = o1;  zg = r0v; zo = r1v; }
                else        { zi = r2v; zf = r3v; zg = o2;  zo = o3;  }
                float4 p4 = pv[mf][n8];
                zi += p4.x; zf += p4.y; zg += p4.z; zo += p4.w;
                float ig = 1.f / (1.f + __expf(-zi));
                float fg = 1.f / (1.f + __expf(-zf));
                float gg = tanhf(zg);
                float og = 1.f / (1.f + __expf(-zo));
                float cc = fg * cst[mf][n8] + ig * gg;
                cst[mf][n8] = cc;
                float h = og * tanhf(cc);

                int b = wm * 32 + mf * 16 + gid + (isodd ? 8 : 0);
                int u = cta * 16 + wn * 4 + n8 * 2 + (lpair >> 1);
                uint16_t hh16, hl16;
                split_h16(h, hh16, hl16);
                hhw[b * U_ + u] = hh16;
                hlw[b * U_ + u] = hl16;
                sOut[b * 16 + (u & 15)] = h;
            }
        }

        __syncthreads();                 // h stores issued + sOut visible

        // coalesced out stores (overlap barrier wait; fire-and-forget)
        {
            int b = tid >> 2;
            int ul = (tid & 3) * 4;
            float4 hv = *(const float4*)(sOut + b * 16 + ul);
            int tout = dir ? (T_ - 1 - t) : t;
            *(float4*)(out + ((size_t)b * T_ + tout) * (2 * U_) + dir * U_ + cta * 16 + ul) = hv;
        }

        if (tid == 0) {
            __threadfence();
            atomicAdd(bar, 1u);
            unsigned target = (unsigned)(t + 1) * 16u;
            unsigned v;
            do {
                asm volatile("ld.global.acquire.gpu.u32 %0, [%1];" : "=r"(v) : "l"(bar));
            } while (v < target);
        }
        __syncthreads();
    }
}

// ---------------- launcher ----------------
extern "C" void kernel_launch(void* const* d_in, const int* in_sizes, int n_in,
                              void* d_out, int out_size)
{
    const float* inputs = (const float*)d_in[0];
    const float* convk  = (const float*)d_in[1];
    const float* convb  = (const float*)d_in[2];
    const float* bng    = (const float*)d_in[3];
    const float* bnb    = (const float*)d_in[4];
    const float* bnm    = (const float*)d_in[5];
    const float* bnv    = (const float*)d_in[6];
    const float* wk_f   = (const float*)d_in[7];
    const float* wr_f   = (const float*)d_in[8];
    const float* bi_f   = (const float*)d_in[9];
    const float* wk_b   = (const float*)d_in[10];
    const float* wr_b   = (const float*)d_in[11];
    const float* bi_b   = (const float*)d_in[12];
    float* out = (float*)d_out;

    uint16_t *x0, *x1, *wch, *wcl, *wlh, *wll;
    float *pre_f, *pre_b;
    cudaGetSymbolAddress((void**)&x0, g_x0);
    cudaGetSymbolAddress((void**)&x1, g_x1);
    cudaGetSymbolAddress((void**)&wch, g_wch);
    cudaGetSymbolAddress((void**)&wcl, g_wcl);
    cudaGetSymbolAddress((void**)&wlh, g_wlh);
    cudaGetSymbolAddress((void**)&wll, g_wll);
    cudaGetSymbolAddress((void**)&pre_f, g_pre_f);
    cudaGetSymbolAddress((void**)&pre_b, g_pre_b);

    cudaFuncSetAttribute(mma_gemm_conv, cudaFuncAttributeMaxDynamicSharedMemorySize, GSMEM);
    cudaFuncSetAttribute(mma_gemm_pre,  cudaFuncAttributeMaxDynamicSharedMemorySize, GSMEM);
    cudaFuncSetAttribute(lstm_tc_kernel, cudaFuncAttributeMaxDynamicSharedMemorySize, LSMEM);

    prep_kernel<<<8192, 256>>>(inputs, convk, wk_f, wk_b, wr_f, wr_b);

    const size_t wcs = (size_t)512 * 2560;
    dim3 gc(D_ / BN, T_ / BM, B_);
    mma_gemm_conv<<<gc, 256, GSMEM>>>(x0, wch + 0 * wcs, wcl + 0 * wcs,
                                      convb + 0 * D_, bng + 0 * D_, bnb + 0 * D_,
                                      bnm + 0 * D_, bnv + 0 * D_, x1);
    mma_gemm_conv<<<gc, 256, GSMEM>>>(x1, wch + 1 * wcs, wcl + 1 * wcs,
                                      convb + 1 * D_, bng + 1 * D_, bnb + 1 * D_,
                                      bnm + 1 * D_, bnv + 1 * D_, x0);
    mma_gemm_conv<<<gc, 256, GSMEM>>>(x0, wch + 2 * wcs, wcl + 2 * wcs,
                                      convb + 2 * D_, bng + 2 * D_, bnb + 2 * D_,
                                      bnm + 2 * D_, bnv + 2 * D_, x1);

    const size_t wls = (size_t)1024 * 512;
    dim3 gl(16, T_ / BM, B_);
    mma_gemm_pre<<<gl, 256, GSMEM>>>(x1 + 2 * D_,
                                     wlh + 0 * wls, wll + 0 * wls,
                                     wlh + 1 * wls, wll + 1 * wls,
                                     bi_f, bi_b, pre_f, pre_b);

    lstm_tc_kernel<<<32, 256, LSMEM>>>(pre_f, pre_b, out);
}

// round 15
// speedup vs baseline: 1.6144x; 1.1647x over previous
#include <cuda_runtime.h>
#include <cuda_fp16.h>
#include <cstdint>
#include <math.h>

#define B_    64
#define T_    1024
#define D_    512
#define KTAP  5
#define U_    256
#define G4_   1024
#define TP_   (T_ + 4)
#define XPD_  (TP_ * D_)

#define BM    128
#define BN    128
#define KC    32
#define ROWB  80
#define TILEB (128 * ROWB)
#define CSTAGEB (2 * TILEB)          // A + Bh per stage
#define CNSTG 4
#define CGSMEM (CNSTG * CSTAGEB)     // 80 KB -> 2 CTAs/SM

// lstm tc kernel tiles: 64 rows x 80B = 5120 B
#define LTILE 5120
#define LOUTOFF (32 * LTILE)
#define LSMEM (LOUTOFF + 4096)

// ---------------- scratch ----------------
__device__ uint16_t g_x0[(size_t)B_ * XPD_];
__device__ uint16_t g_x1[(size_t)B_ * XPD_];
__device__ uint16_t g_wch[(size_t)3 * 512 * 2560];  // conv weights fp16 [i][n][kk]
__device__ uint16_t g_wlh[(size_t)2 * 1024 * 512];  // lstm kernels fp16 [dir][n][d]
__device__ uint16_t g_wrh[(size_t)2 * 1024 * 256];  // recurrent W hi [dir][colp][k]
__device__ uint16_t g_wrl[(size_t)2 * 1024 * 256];  // recurrent W lo
__device__ float    g_pre_f[(size_t)T_ * B_ * G4_]; // colp-permuted [t][b][4u+g]
__device__ float    g_pre_b[(size_t)T_ * B_ * G4_];
__device__ uint16_t g_hh[2][2][B_ * U_];
__device__ uint16_t g_hl[2][2][B_ * U_];
__device__ unsigned g_bar[2];

// ---------------- helpers ----------------
__device__ __forceinline__ uint32_t smem_u32(const void* p) {
    uint32_t a;
    asm("{ .reg .u64 t; cvta.to.shared.u64 t, %1; cvt.u32.u64 %0, t; }" : "=r"(a) : "l"(p));
    return a;
}
__device__ __forceinline__ uint16_t f2h(float v) {
    return __half_as_ushort(__float2half(v));
}
__device__ __forceinline__ void split_h16(float v, uint16_t& h, uint16_t& l) {
    __half hh = __float2half(v);
    float hf = __half2float(hh);
    h = __half_as_ushort(hh);
    l = __half_as_ushort(__float2half(v - hf));
}
#define CP16(dst, src) \
    asm volatile("cp.async.cg.shared.global [%0], [%1], 16;" :: "r"(dst), "l"(src))
#define CP_COMMIT() asm volatile("cp.async.commit_group;" ::: "memory")
#define CP_WAIT(N)  asm volatile("cp.async.wait_group %0;" :: "n"(N) : "memory")
#define LDM_X4(R0, R1, R2, R3, ADDR)                                            \
    asm volatile("ldmatrix.sync.aligned.m8n8.x4.shared.b16 {%0,%1,%2,%3}, [%4];"\
        : "=r"(R0), "=r"(R1), "=r"(R2), "=r"(R3) : "r"(ADDR))
__device__ __forceinline__ void mma_f16(float* c, const uint32_t* a, const uint32_t* b) {
    asm volatile(
        "mma.sync.aligned.m16n8k16.row.col.f32.f16.f16.f32 "
        "{%0,%1,%2,%3}, {%4,%5,%6,%7}, {%8,%9}, {%0,%1,%2,%3};"
        : "+f"(c[0]), "+f"(c[1]), "+f"(c[2]), "+f"(c[3])
        : "r"(a[0]), "r"(a[1]), "r"(a[2]), "r"(a[3]), "r"(b[0]), "r"(b[1]));
}

// ---------------- fused prep ----------------
__global__ void prep_kernel(const float* __restrict__ in,
                            const float* __restrict__ convk,
                            const float* __restrict__ wkf,
                            const float* __restrict__ wkb,
                            const float* __restrict__ wrf,
                            const float* __restrict__ wrb) {
    const size_t stride = (size_t)gridDim.x * blockDim.x;
    const size_t tid0 = (size_t)blockIdx.x * blockDim.x + threadIdx.x;

    for (size_t idx = tid0; idx < (size_t)B_ * 4 * D_; idx += stride) {
        int b = (int)(idx / (4 * D_));
        int r = (int)((idx / D_) & 3);
        int d = (int)(idx % D_);
        int row = (r < 2) ? r : (TP_ - 4 + r);
        size_t o = (size_t)b * XPD_ + (size_t)row * D_ + d;
        g_x0[o] = 0; g_x1[o] = 0;
    }
    for (size_t idx = tid0; idx < (size_t)2 * 2 * B_ * U_ / 2; idx += stride) {
        ((uint32_t*)g_hh)[idx] = 0u;
        ((uint32_t*)g_hl)[idx] = 0u;
    }
    if (tid0 < 2) g_bar[tid0] = 0u;

    for (size_t idx = tid0; idx < (size_t)B_ * T_ * D_; idx += stride) {
        size_t b = idx / ((size_t)T_ * D_);
        size_t r = idx % ((size_t)T_ * D_);
        size_t t = r / D_, d = r % D_;
        g_x0[b * XPD_ + (t + 2) * D_ + d] = f2h(in[idx]);
    }

    const size_t CONVN = (size_t)3 * 512 * 2560;
    const size_t LSTMN = (size_t)1024 * 512;
    for (size_t idx = tid0; idx < CONVN + 2 * LSTMN; idx += stride) {
        if (idx < CONVN) {
            size_t i = idx / ((size_t)512 * 2560);
            size_t r = idx % ((size_t)512 * 2560);
            size_t n = r / 2560, kk = r % 2560;
            size_t tap = kk >> 9, din = kk & 511;
            g_wch[idx] = f2h(convk[(((i * KTAP + tap) * D_) + din) * D_ + n]);
        } else if (idx < CONVN + LSTMN) {
            size_t j = idx - CONVN;
            size_t n = j >> 9, d = j & 511;
            g_wlh[j] = f2h(wkf[d * G4_ + n]);
        } else {
            size_t j = idx - CONVN - LSTMN;
            size_t n = j >> 9, d = j & 511;
            g_wlh[LSTMN + j] = f2h(wkb[d * G4_ + n]);
        }
    }

    const size_t WRN = (size_t)2 * 1024 * 256;
    for (size_t idx = tid0; idx < WRN; idx += stride) {
        size_t dir = idx >> 18;
        size_t r = idx & 262143;
        size_t colp = r >> 8, k = r & 255;
        size_t u = colp >> 2, g = colp & 3;
        const float* wr = dir ? wrb : wrf;
        uint16_t h, l;
        split_h16(wr[k * G4_ + g * U_ + u], h, l);
        g_wrh[idx] = h; g_wrl[idx] = l;
    }
}

// ---------------- fp16 1-term warp-MMA conv GEMM, 4-stage pipeline ----------------
__global__ __launch_bounds__(256, 2) void mma_gemm_conv(
    const uint16_t* __restrict__ Ap,
    const uint16_t* __restrict__ Bh,
    const float* __restrict__ bias,
    const float* __restrict__ bng, const float* __restrict__ bnb,
    const float* __restrict__ bnm, const float* __restrict__ bnv,
    uint16_t* __restrict__ Cp)
{
    extern __shared__ char smraw[];
    const uint32_t sbase = smem_u32(smraw);
    const int KKtot = KTAP * D_;

    const int tid = threadIdx.x;
    const int wid = tid >> 5, lane = tid & 31;
    const int bz = blockIdx.z;
    const int t0 = blockIdx.y * BM;
    const int n0 = blockIdx.x * BN;
    const int wm = wid & 1;
    const int wn = wid >> 1;

    const uint32_t a_off = (uint32_t)((wm * 64 + (lane & 15)) * ROWB + (lane >> 4) * 16);
    const uint32_t b_off = (uint32_t)((wn * 32 + (lane & 7) + ((lane >> 4) << 3)) * ROWB
                                      + ((lane >> 3) & 1) * 16);

    const uint16_t* Ab = Ap + (size_t)bz * XPD_;
    const int NCH = KKtot / KC;

    float cacc[4][4][4];
#pragma unroll
    for (int i = 0; i < 4; i++)
#pragma unroll
        for (int j = 0; j < 4; j++)
#pragma unroll
            for (int q = 0; q < 4; q++) cacc[i][j][q] = 0.f;

    auto issue = [&](int cc) {
        const int st = cc % CNSTG;
        const int kk0 = cc * KC;
        const int tap = kk0 >> 9;
        const int d0 = kk0 & 511;
        const uint32_t sb = sbase + st * CSTAGEB;
#pragma unroll
        for (int half = 0; half < 2; half++) {
            const int s = tid + half * 256;
            const int row = s >> 2, seg = s & 3;
            const uint32_t doff = (uint32_t)(row * ROWB + seg * 16);
            const size_t aoff = (size_t)(t0 + row + tap) * D_ + d0 + seg * 8;
            const size_t boff = (size_t)(n0 + row) * KKtot + kk0 + seg * 8;
            CP16(sb + doff,         Ab + aoff);
            CP16(sb + TILEB + doff, Bh + boff);
        }
        CP_COMMIT();
    };

    auto compute = [&](int st) {
        const uint32_t SB = sbase + st * CSTAGEB;
#pragma unroll
        for (int k16 = 0; k16 < 2; k16++) {
            const uint32_t kof = k16 * 32;
            uint32_t bh[4][2];
#pragma unroll
            for (int nfp = 0; nfp < 2; nfp++) {
                uint32_t bd = SB + TILEB + b_off + nfp * (16 * ROWB) + kof;
                LDM_X4(bh[2 * nfp][0], bh[2 * nfp][1], bh[2 * nfp + 1][0], bh[2 * nfp + 1][1], bd);
            }
#pragma unroll
            for (int mf = 0; mf < 4; mf++) {
                uint32_t af[4];
                uint32_t ad = SB + a_off + mf * (16 * ROWB) + kof;
                LDM_X4(af[0], af[1], af[2], af[3], ad);
#pragma unroll
                for (int nf = 0; nf < 4; nf++)
                    mma_f16(cacc[mf][nf], af, bh[nf]);
            }
        }
    };

    issue(0);
    issue(1);
    issue(2);
    for (int cc = 0; cc < NCH; cc++) {
        CP_WAIT(2);
        __syncthreads();
        if (cc + 3 < NCH) issue(cc + 3);
        else CP_COMMIT();
        compute(cc % CNSTG);
    }

    const int r0 = lane >> 2;
    const int cq = (lane & 3) * 2;
    float mul0[4], mul1[4], add0[4], add1[4];
#pragma unroll
    for (int nf = 0; nf < 4; nf++) {
        int n = n0 + wn * 32 + nf * 8 + cq;
        float b0 = __ldg(&bias[n]), b1 = __ldg(&bias[n + 1]);
        float s0 = __ldg(&bng[n]) * rsqrtf(__ldg(&bnv[n]) + 1e-3f);
        float s1 = __ldg(&bng[n + 1]) * rsqrtf(__ldg(&bnv[n + 1]) + 1e-3f);
        mul0[nf] = s0; mul1[nf] = s1;
        add0[nf] = s0 * (b0 - __ldg(&bnm[n])) + __ldg(&bnb[n]);
        add1[nf] = s1 * (b1 - __ldg(&bnm[n + 1])) + __ldg(&bnb[n + 1]);
    }
#pragma unroll
    for (int mf = 0; mf < 4; mf++) {
#pragma unroll
        for (int half = 0; half < 2; half++) {
            int m = wm * 64 + mf * 16 + r0 + half * 8;
#pragma unroll
            for (int nf = 0; nf < 4; nf++) {
                float v0 = fmaxf(fmaf(cacc[mf][nf][2 * half + 0], mul0[nf], add0[nf]), 0.f);
                float v1 = fmaxf(fmaf(cacc[mf][nf][2 * half + 1], mul1[nf], add1[nf]), 0.f);
                int nc = n0 + wn * 32 + nf * 8 + cq;
                size_t off = (size_t)bz * XPD_ + (size_t)(t0 + m + 2) * D_ + nc;
                *(uint32_t*)(Cp + off) = (uint32_t)f2h(v0) | ((uint32_t)f2h(v1) << 16);
            }
        }
    }
}

// ---------------- fused fw+bw LSTM-pre GEMM (1-term, colp-permuted out) ----------------
__global__ __launch_bounds__(256, 2) void mma_gemm_pre(
    const uint16_t* __restrict__ Ap,
    const uint16_t* __restrict__ Bhf, const uint16_t* __restrict__ Bhb,
    const float* __restrict__ bias_f, const float* __restrict__ bias_b,
    float* __restrict__ pre_f, float* __restrict__ pre_b)
{
    extern __shared__ char smraw[];
    const uint32_t sbase = smem_u32(smraw);
    const int KKtot = D_;

    const int tid = threadIdx.x;
    const int wid = tid >> 5, lane = tid & 31;
    const int bz = blockIdx.z;
    const int t0 = blockIdx.y * BM;
    const int fw = (blockIdx.x < 8);
    const int n0 = (blockIdx.x & 7) * BN;
    const int wm = wid & 1;
    const int wn = wid >> 1;

    const uint16_t* Bh = fw ? Bhf : Bhb;
    const float* bias = fw ? bias_f : bias_b;
    float* Cf = fw ? pre_f : pre_b;

    const uint32_t a_off = (uint32_t)((wm * 64 + (lane & 15)) * ROWB + (lane >> 4) * 16);
    const uint32_t b_off = (uint32_t)((wn * 32 + (lane & 7) + ((lane >> 4) << 3)) * ROWB
                                      + ((lane >> 3) & 1) * 16);

    const uint16_t* Ab = Ap + (size_t)bz * XPD_;
    const int NCH = KKtot / KC;

    float cacc[4][4][4];
#pragma unroll
    for (int i = 0; i < 4; i++)
#pragma unroll
        for (int j = 0; j < 4; j++)
#pragma unroll
            for (int q = 0; q < 4; q++) cacc[i][j][q] = 0.f;

    auto issue = [&](int cc) {
        const int st = cc % CNSTG;
        const int kk0 = cc * KC;
        const uint32_t sb = sbase + st * CSTAGEB;
#pragma unroll
        for (int half = 0; half < 2; half++) {
            const int s = tid + half * 256;
            const int row = s >> 2, seg = s & 3;
            const uint32_t doff = (uint32_t)(row * ROWB + seg * 16);
            const size_t aoff = (size_t)(t0 + row) * D_ + kk0 + seg * 8;
            const size_t boff = (size_t)(n0 + row) * KKtot + kk0 + seg * 8;
            CP16(sb + doff,         Ab + aoff);
            CP16(sb + TILEB + doff, Bh + boff);
        }
        CP_COMMIT();
    };

    auto compute = [&](int st) {
        const uint32_t SB = sbase + st * CSTAGEB;
#pragma unroll
        for (int k16 = 0; k16 < 2; k16++) {
            const uint32_t kof = k16 * 32;
            uint32_t bh[4][2];
#pragma unroll
            for (int nfp = 0; nfp < 2; nfp++) {
                uint32_t bd = SB + TILEB + b_off + nfp * (16 * ROWB) + kof;
                LDM_X4(bh[2 * nfp][0], bh[2 * nfp][1], bh[2 * nfp + 1][0], bh[2 * nfp + 1][1], bd);
            }
#pragma unroll
            for (int mf = 0; mf < 4; mf++) {
                uint32_t af[4];
                uint32_t ad = SB + a_off + mf * (16 * ROWB) + kof;
                LDM_X4(af[0], af[1], af[2], af[3], ad);
#pragma unroll
                for (int nf = 0; nf < 4; nf++)
                    mma_f16(cacc[mf][nf], af, bh[nf]);
            }
        }
    };

    issue(0);
    issue(1);
    issue(2);
    for (int cc = 0; cc < NCH; cc++) {
        CP_WAIT(2);
        __syncthreads();
        if (cc + 3 < NCH) issue(cc + 3);
        else CP_COMMIT();
        compute(cc % CNSTG);
    }

    const int r0 = lane >> 2;
    const int cq = (lane & 3) * 2;
    float add0[4], add1[4];
#pragma unroll
    for (int nf = 0; nf < 4; nf++) {
        int n = n0 + wn * 32 + nf * 8 + cq;
        add0[nf] = __ldg(&bias[n]);
        add1[nf] = __ldg(&bias[n + 1]);
    }
#pragma unroll
    for (int mf = 0; mf < 4; mf++) {
#pragma unroll
        for (int half = 0; half < 2; half++) {
            int m = wm * 64 + mf * 16 + r0 + half * 8;
            int t = t0 + m;
            size_t rowoff = fw ? ((size_t)t * B_ + bz) * G4_
                               : ((size_t)(T_ - 1 - t) * B_ + bz) * G4_;
#pragma unroll
            for (int nf = 0; nf < 4; nf++) {
                int nc = n0 + wn * 32 + nf * 8 + cq;
                int u = nc & 255, g = nc >> 8;
                float v0 = cacc[mf][nf][2 * half + 0] + add0[nf];
                float v1 = cacc[mf][nf][2 * half + 1] + add1[nf];
                Cf[rowoff + 4 * u + g] = v0;
                Cf[rowoff + 4 * (u + 1) + g] = v1;
            }
        }
    }
}

// ---------------- tensor-core bi-LSTM recurrence (R14, unchanged) ----------------
__global__ __launch_bounds__(256) void lstm_tc_kernel(
    const float* __restrict__ pre_f, const float* __restrict__ pre_b,
    float* __restrict__ out)
{
    extern __shared__ char smraw[];
    const uint32_t sbase = smem_u32(smraw);
    float* sOut = (float*)(smraw + LOUTOFF);

    const int bx = blockIdx.x;
    const int dir = bx >> 4;
    const int cta = bx & 15;
    const float* pre = dir ? pre_b : pre_f;
    unsigned* bar = &g_bar[dir];

    const int tid = threadIdx.x;
    const int wid = tid >> 5, lane = tid & 31;
    const int wm = wid & 1;
    const int wn = wid >> 1;
    const int gid = lane >> 2;
    const int lpair = lane & 3;
    const int isodd = lane & 1;

    {
        const uint16_t* wh = g_wrh + (size_t)dir * 1024 * 256 + (size_t)cta * 64 * 256;
        const uint16_t* wl = g_wrl + (size_t)dir * 1024 * 256 + (size_t)cta * 64 * 256;
        for (int s = tid; s < 4096; s += 256) {
            int tile = s >> 8, row = (s >> 2) & 63, seg = s & 3;
            int p = tile & 1, c = tile >> 1;
            const uint16_t* src = (p ? wl : wh) + row * 256 + c * 32 + seg * 8;
            uint4 v = *(const uint4*)src;
            *(uint4*)(smraw + 81920 + (c * 2 + p) * LTILE + row * ROWB + seg * 16) = v;
        }
    }

    const uint32_t a_off = (uint32_t)((wm * 32 + (lane & 15)) * ROWB + (lane >> 4) * 16);
    const uint32_t b_off = (uint32_t)(81920 + (wn * 16 + (lane & 7) + ((lane >> 4) << 3)) * ROWB
                                      + ((lane >> 3) & 1) * 16);

    float cst[2][2] = {{0.f, 0.f}, {0.f, 0.f}};
    __syncthreads();

    for (int t = 0; t < T_; t++) {
        float4 pv[2][2];
#pragma unroll
        for (int mf = 0; mf < 2; mf++)
#pragma unroll
            for (int n8 = 0; n8 < 2; n8++) {
                int b = wm * 32 + mf * 16 + gid + (isodd ? 8 : 0);
                int u = cta * 16 + wn * 4 + n8 * 2 + (lpair >> 1);
                pv[mf][n8] = __ldg((const float4*)(pre + ((size_t)t * B_ + b) * G4_ + 4 * u));
            }

        const int slot = (t + 1) & 1;
        const uint16_t* hhr = &g_hh[dir][slot][0];
        const uint16_t* hlr = &g_hl[dir][slot][0];
#pragma unroll
        for (int half = 0; half < 2; half++) {
#pragma unroll
            for (int j = 0; j < 8; j++) {
                int s = tid + (half * 8 + j) * 256;
                int tile = s >> 8, row = (s >> 2) & 63, seg = s & 3;
                int p = tile & 1, c = tile >> 1;
                const uint16_t* src = (p ? hlr : hhr) + row * 256 + c * 32 + seg * 8;
                CP16(sbase + (c * 2 + p) * LTILE + (uint32_t)(row * ROWB + seg * 16), src);
            }
            CP_COMMIT();
        }

        float acc[2][2][4];
#pragma unroll
        for (int i = 0; i < 2; i++)
#pragma unroll
            for (int j = 0; j < 2; j++)
#pragma unroll
                for (int q = 0; q < 4; q++) acc[i][j][q] = 0.f;

        CP_WAIT(1);
        __syncthreads();
#pragma unroll
        for (int c = 0; c < 4; c++) {
#pragma unroll
            for (int k16 = 0; k16 < 2; k16++) {
                const uint32_t kof = k16 * 32;
                uint32_t bh[2][2], bl[2][2];
                LDM_X4(bh[0][0], bh[0][1], bh[1][0], bh[1][1],
                       sbase + b_off + (c * 2 + 0) * LTILE + kof);
                LDM_X4(bl[0][0], bl[0][1], bl[1][0], bl[1][1],
                       sbase + b_off + (c * 2 + 1) * LTILE + kof);
#pragma unroll
                for (int mf = 0; mf < 2; mf++) {
                    uint32_t ah[4], al[4];
                    LDM_X4(ah[0], ah[1], ah[2], ah[3],
                           sbase + (c * 2 + 0) * LTILE + a_off + mf * (16 * ROWB) + kof);
                    LDM_X4(al[0], al[1], al[2], al[3],
                           sbase + (c * 2 + 1) * LTILE + a_off + mf * (16 * ROWB) + kof);
#pragma unroll
                    for (int n8 = 0; n8 < 2; n8++) {
                        mma_f16(acc[mf][n8], ah, bh[n8]);
                        mma_f16(acc[mf][n8], al, bh[n8]);
                        mma_f16(acc[mf][n8], ah, bl[n8]);
                    }
                }
            }
        }
        CP_WAIT(0);
        __syncthreads();
#pragma unroll
        for (int c = 4; c < 8; c++) {
#pragma unroll
            for (int k16 = 0; k16 < 2; k16++) {
                const uint32_t kof = k16 * 32;
                uint32_t bh[2][2], bl[2][2];
                LDM_X4(bh[0][0], bh[0][1], bh[1][0], bh[1][1],
                       sbase + b_off + (c * 2 + 0) * LTILE + kof);
                LDM_X4(bl[0][0], bl[0][1], bl[1][0], bl[1][1],
                       sbase + b_off + (c * 2 + 1) * LTILE + kof);
#pragma unroll
                for (int mf = 0; mf < 2; mf++) {
                    uint32_t ah[4], al[4];
                    LDM_X4(ah[0], ah[1], ah[2], ah[3],
                           sbase + (c * 2 + 0) * LTILE + a_off + mf * (16 * ROWB) + kof);
                    LDM_X4(al[0], al[1], al[2], al[3],
                           sbase + (c * 2 + 1) * LTILE + a_off + mf * (16 * ROWB) + kof);
#pragma unroll
                    for (int n8 = 0; n8 < 2; n8++) {
                        mma_f16(acc[mf][n8], ah, bh[n8]);
                        mma_f16(acc[mf][n8], al, bh[n8]);
                        mma_f16(acc[mf][n8], ah, bl[n8]);
                    }
                }
            }
        }
        __syncthreads();

        uint16_t* hhw = &g_hh[dir][t & 1][0];
        uint16_t* hlw = &g_hl[dir][t & 1][0];
#pragma unroll
        for (int mf = 0; mf < 2; mf++) {
#pragma unroll
            for (int n8 = 0; n8 < 2; n8++) {
                float o0 = acc[mf][n8][0], o1 = acc[mf][n8][1];
                float o2 = acc[mf][n8][2], o3 = acc[mf][n8][3];
                float r0v = __shfl_xor_sync(0xFFFFFFFFu, o0, 1);
                float r1v = __shfl_xor_sync(0xFFFFFFFFu, o1, 1);
                float r2v = __shfl_xor_sync(0xFFFFFFFFu, o2, 1);
                float r3v = __shfl_xor_sync(0xFFFFFFFFu, o3, 1);
                float zi, zf, zg, zo;
                if (!isodd) { zi = o0;  zf = o1;  zg = r0v; zo = r1v; }
                else        { zi = r2v; zf = r3v; zg = o2;  zo = o3;  }
                float4 p4 = pv[mf][n8];
                zi += p4.x; zf += p4.y; zg += p4.z; zo += p4.w;
                float ig = 1.f / (1.f + __expf(-zi));
                float fg = 1.f / (1.f + __expf(-zf));
                float gg = tanhf(zg);
                float og = 1.f / (1.f + __expf(-zo));
                float cc = fg * cst[mf][n8] + ig * gg;
                cst[mf][n8] = cc;
                float h = og * tanhf(cc);

                int b = wm * 32 + mf * 16 + gid + (isodd ? 8 : 0);
                int u = cta * 16 + wn * 4 + n8 * 2 + (lpair >> 1);
                uint16_t hh16, hl16;
                split_h16(h, hh16, hl16);
                hhw[b * U_ + u] = hh16;
                hlw[b * U_ + u] = hl16;
                sOut[b * 16 + (u & 15)] = h;
            }
        }

        __syncthreads();

        {
            int b = tid >> 2;
            int ul = (tid & 3) * 4;
            float4 hv = *(const float4*)(sOut + b * 16 + ul);
            int tout = dir ? (T_ - 1 - t) : t;
            *(float4*)(out + ((size_t)b * T_ + tout) * (2 * U_) + dir * U_ + cta * 16 + ul) = hv;
        }

        if (tid == 0) {
            __threadfence();
            atomicAdd(bar, 1u);
            unsigned target = (unsigned)(t + 1) * 16u;
            unsigned v;
            do {
                asm volatile("ld.global.acquire.gpu.u32 %0, [%1];" : "=r"(v) : "l"(bar));
            } while (v < target);
        }
        __syncthreads();
    }
}

// ---------------- launcher ----------------
extern "C" void kernel_launch(void* const* d_in, const int* in_sizes, int n_in,
                              void* d_out, int out_size)
{
    const float* inputs = (const float*)d_in[0];
    const float* convk  = (const float*)d_in[1];
    const float* convb  = (const float*)d_in[2];
    const float* bng    = (const float*)d_in[3];
    const float* bnb    = (const float*)d_in[4];
    const float* bnm    = (const float*)d_in[5];
    const float* bnv    = (const float*)d_in[6];
    const float* wk_f   = (const float*)d_in[7];
    const float* wr_f   = (const float*)d_in[8];
    const float* bi_f   = (const float*)d_in[9];
    const float* wk_b   = (const float*)d_in[10];
    const float* wr_b   = (const float*)d_in[11];
    const float* bi_b   = (const float*)d_in[12];
    float* out = (float*)d_out;

    uint16_t *x0, *x1, *wch, *wlh;
    float *pre_f, *pre_b;
    cudaGetSymbolAddress((void**)&x0, g_x0);
    cudaGetSymbolAddress((void**)&x1, g_x1);
    cudaGetSymbolAddress((void**)&wch, g_wch);
    cudaGetSymbolAddress((void**)&wlh, g_wlh);
    cudaGetSymbolAddress((void**)&pre_f, g_pre_f);
    cudaGetSymbolAddress((void**)&pre_b, g_pre_b);

    cudaFuncSetAttribute(mma_gemm_conv, cudaFuncAttributeMaxDynamicSharedMemorySize, CGSMEM);
    cudaFuncSetAttribute(mma_gemm_pre,  cudaFuncAttributeMaxDynamicSharedMemorySize, CGSMEM);
    cudaFuncSetAttribute(lstm_tc_kernel, cudaFuncAttributeMaxDynamicSharedMemorySize, LSMEM);

    prep_kernel<<<8192, 256>>>(inputs, convk, wk_f, wk_b, wr_f, wr_b);

    const size_t wcs = (size_t)512 * 2560;
    dim3 gc(D_ / BN, T_ / BM, B_);
    mma_gemm_conv<<<gc, 256, CGSMEM>>>(x0, wch + 0 * wcs,
                                       convb + 0 * D_, bng + 0 * D_, bnb + 0 * D_,
                                       bnm + 0 * D_, bnv + 0 * D_, x1);
    mma_gemm_conv<<<gc, 256, CGSMEM>>>(x1, wch + 1 * wcs,
                                       convb + 1 * D_, bng + 1 * D_, bnb + 1 * D_,
                                       bnm + 1 * D_, bnv + 1 * D_, x0);
    mma_gemm_conv<<<gc, 256, CGSMEM>>>(x0, wch + 2 * wcs,
                                       convb + 2 * D_, bng + 2 * D_, bnb + 2 * D_,
                                       bnm + 2 * D_, bnv + 2 * D_, x1);

    const size_t wls = (size_t)1024 * 512;
    dim3 gl(16, T_ / BM, B_);
    mma_gemm_pre<<<gl, 256, CGSMEM>>>(x1 + 2 * D_,
                                      wlh + 0 * wls, wlh + 1 * wls,
                                      bi_f, bi_b, pre_f, pre_b);

    lstm_tc_kernel<<<32, 256, LSMEM>>>(pre_f, pre_b, out);
}

// round 16
// speedup vs baseline: 1.9080x; 1.1819x over previous
#include <cuda_runtime.h>
#include <cuda_fp16.h>
#include <cstdint>
#include <math.h>

#define B_    64
#define T_    1024
#define D_    512
#define KTAP  5
#define U_    256
#define G4_   1024
#define TP_   (T_ + 4)
#define XPD_  (TP_ * D_)

#define BM    128
#define BN    128
#define KC    32
#define ROWB  80
#define TILEB (128 * ROWB)
#define CSTAGEB (2 * TILEB)          // A + Bh per stage
#define CNSTG 4
#define CGSMEM (CNSTG * CSTAGEB)     // 80 KB -> 2 CTAs/SM

// lstm tc kernel: H tiles (8, hi only) then W tiles (16, hi+lo)
#define LTILE 5120
#define LWOFF (8 * LTILE)            // 40960
#define LOUTOFF (LWOFF + 16 * LTILE) // 122880
#define LSMEM (LOUTOFF + 4096)       // 126976

// ---------------- scratch ----------------
__device__ uint16_t g_x0[(size_t)B_ * XPD_];
__device__ uint16_t g_x1[(size_t)B_ * XPD_];
__device__ uint16_t g_wch[(size_t)3 * 512 * 2560];  // conv weights fp16 [i][n][kk]
__device__ uint16_t g_wlh[(size_t)2 * 1024 * 512];  // lstm kernels fp16 [dir][n][d]
__device__ uint16_t g_wrh[(size_t)2 * 1024 * 256];  // recurrent W hi [dir][colp][k]
__device__ uint16_t g_wrl[(size_t)2 * 1024 * 256];  // recurrent W lo
__device__ float    g_pre_f[(size_t)T_ * B_ * G4_]; // colp-permuted [t][b][4u+g]
__device__ float    g_pre_b[(size_t)T_ * B_ * G4_];
__device__ uint16_t g_hh[2][2][B_ * U_];            // h fp16 [dir][slot][b*256+u]
__device__ unsigned g_bar[2];

// ---------------- helpers ----------------
__device__ __forceinline__ uint32_t smem_u32(const void* p) {
    uint32_t a;
    asm("{ .reg .u64 t; cvta.to.shared.u64 t, %1; cvt.u32.u64 %0, t; }" : "=r"(a) : "l"(p));
    return a;
}
__device__ __forceinline__ uint16_t f2h(float v) {
    return __half_as_ushort(__float2half(v));
}
__device__ __forceinline__ void split_h16(float v, uint16_t& h, uint16_t& l) {
    __half hh = __float2half(v);
    float hf = __half2float(hh);
    h = __half_as_ushort(hh);
    l = __half_as_ushort(__float2half(v - hf));
}
#define CP16(dst, src) \
    asm volatile("cp.async.cg.shared.global [%0], [%1], 16;" :: "r"(dst), "l"(src))
#define CP_COMMIT() asm volatile("cp.async.commit_group;" ::: "memory")
#define CP_WAIT(N)  asm volatile("cp.async.wait_group %0;" :: "n"(N) : "memory")
#define LDM_X4(R0, R1, R2, R3, ADDR)                                            \
    asm volatile("ldmatrix.sync.aligned.m8n8.x4.shared.b16 {%0,%1,%2,%3}, [%4];"\
        : "=r"(R0), "=r"(R1), "=r"(R2), "=r"(R3) : "r"(ADDR))
__device__ __forceinline__ void mma_f16(float* c, const uint32_t* a, const uint32_t* b) {
    asm volatile(
        "mma.sync.aligned.m16n8k16.row.col.f32.f16.f16.f32 "
        "{%0,%1,%2,%3}, {%4,%5,%6,%7}, {%8,%9}, {%0,%1,%2,%3};"
        : "+f"(c[0]), "+f"(c[1]), "+f"(c[2]), "+f"(c[3])
        : "r"(a[0]), "r"(a[1]), "r"(a[2]), "r"(a[3]), "r"(b[0]), "r"(b[1]));
}

// ---------------- fused prep ----------------
__global__ void prep_kernel(const float* __restrict__ in,
                            const float* __restrict__ convk,
                            const float* __restrict__ wkf,
                            const float* __restrict__ wkb,
                            const float* __restrict__ wrf,
                            const float* __restrict__ wrb) {
    const size_t stride = (size_t)gridDim.x * blockDim.x;
    const size_t tid0 = (size_t)blockIdx.x * blockDim.x + threadIdx.x;

    for (size_t idx = tid0; idx < (size_t)B_ * 4 * D_; idx += stride) {
        int b = (int)(idx / (4 * D_));
        int r = (int)((idx / D_) & 3);
        int d = (int)(idx % D_);
        int row = (r < 2) ? r : (TP_ - 4 + r);
        size_t o = (size_t)b * XPD_ + (size_t)row * D_ + d;
        g_x0[o] = 0; g_x1[o] = 0;
    }
    for (size_t idx = tid0; idx < (size_t)2 * 2 * B_ * U_ / 2; idx += stride)
        ((uint32_t*)g_hh)[idx] = 0u;
    if (tid0 < 2) g_bar[tid0] = 0u;

    for (size_t idx = tid0; idx < (size_t)B_ * T_ * D_; idx += stride) {
        size_t b = idx / ((size_t)T_ * D_);
        size_t r = idx % ((size_t)T_ * D_);
        size_t t = r / D_, d = r % D_;
        g_x0[b * XPD_ + (t + 2) * D_ + d] = f2h(in[idx]);
    }

    const size_t CONVN = (size_t)3 * 512 * 2560;
    const size_t LSTMN = (size_t)1024 * 512;
    for (size_t idx = tid0; idx < CONVN + 2 * LSTMN; idx += stride) {
        if (idx < CONVN) {
            size_t i = idx / ((size_t)512 * 2560);
            size_t r = idx % ((size_t)512 * 2560);
            size_t n = r / 2560, kk = r % 2560;
            size_t tap = kk >> 9, din = kk & 511;
            g_wch[idx] = f2h(convk[(((i * KTAP + tap) * D_) + din) * D_ + n]);
        } else if (idx < CONVN + LSTMN) {
            size_t j = idx - CONVN;
            size_t n = j >> 9, d = j & 511;
            g_wlh[j] = f2h(wkf[d * G4_ + n]);
        } else {
            size_t j = idx - CONVN - LSTMN;
            size_t n = j >> 9, d = j & 511;
            g_wlh[LSTMN + j] = f2h(wkb[d * G4_ + n]);
        }
    }

    const size_t WRN = (size_t)2 * 1024 * 256;
    for (size_t idx = tid0; idx < WRN; idx += stride) {
        size_t dir = idx >> 18;
        size_t r = idx & 262143;
        size_t colp = r >> 8, k = r & 255;
        size_t u = colp >> 2, g = colp & 3;
        const float* wr = dir ? wrb : wrf;
        uint16_t h, l;
        split_h16(wr[k * G4_ + g * U_ + u], h, l);
        g_wrh[idx] = h; g_wrl[idx] = l;
    }
}

// ---------------- fp16 1-term warp-MMA conv GEMM, 4-stage pipeline ----------------
__global__ __launch_bounds__(256, 2) void mma_gemm_conv(
    const uint16_t* __restrict__ Ap,
    const uint16_t* __restrict__ Bh,
    const float* __restrict__ bias,
    const float* __restrict__ bng, const float* __restrict__ bnb,
    const float* __restrict__ bnm, const float* __restrict__ bnv,
    uint16_t* __restrict__ Cp)
{
    extern __shared__ char smraw[];
    const uint32_t sbase = smem_u32(smraw);
    const int KKtot = KTAP * D_;

    const int tid = threadIdx.x;
    const int wid = tid >> 5, lane = tid & 31;
    const int bz = blockIdx.z;
    const int t0 = blockIdx.y * BM;
    const int n0 = blockIdx.x * BN;
    const int wm = wid & 1;
    const int wn = wid >> 1;

    const uint32_t a_off = (uint32_t)((wm * 64 + (lane & 15)) * ROWB + (lane >> 4) * 16);
    const uint32_t b_off = (uint32_t)((wn * 32 + (lane & 7) + ((lane >> 4) << 3)) * ROWB
                                      + ((lane >> 3) & 1) * 16);

    const uint16_t* Ab = Ap + (size_t)bz * XPD_;
    const int NCH = KKtot / KC;

    float cacc[4][4][4];
#pragma unroll
    for (int i = 0; i < 4; i++)
#pragma unroll
        for (int j = 0; j < 4; j++)
#pragma unroll
            for (int q = 0; q < 4; q++) cacc[i][j][q] = 0.f;

    auto issue = [&](int cc) {
        const int st = cc % CNSTG;
        const int kk0 = cc * KC;
        const int tap = kk0 >> 9;
        const int d0 = kk0 & 511;
        const uint32_t sb = sbase + st * CSTAGEB;
#pragma unroll
        for (int half = 0; half < 2; half++) {
            const int s = tid + half * 256;
            const int row = s >> 2, seg = s & 3;
            const uint32_t doff = (uint32_t)(row * ROWB + seg * 16);
            const size_t aoff = (size_t)(t0 + row + tap) * D_ + d0 + seg * 8;
            const size_t boff = (size_t)(n0 + row) * KKtot + kk0 + seg * 8;
            CP16(sb + doff,         Ab + aoff);
            CP16(sb + TILEB + doff, Bh + boff);
        }
        CP_COMMIT();
    };

    auto compute = [&](int st) {
        const uint32_t SB = sbase + st * CSTAGEB;
#pragma unroll
        for (int k16 = 0; k16 < 2; k16++) {
            const uint32_t kof = k16 * 32;
            uint32_t bh[4][2];
#pragma unroll
            for (int nfp = 0; nfp < 2; nfp++) {
                uint32_t bd = SB + TILEB + b_off + nfp * (16 * ROWB) + kof;
                LDM_X4(bh[2 * nfp][0], bh[2 * nfp][1], bh[2 * nfp + 1][0], bh[2 * nfp + 1][1], bd);
            }
#pragma unroll
            for (int mf = 0; mf < 4; mf++) {
                uint32_t af[4];
                uint32_t ad = SB + a_off + mf * (16 * ROWB) + kof;
                LDM_X4(af[0], af[1], af[2], af[3], ad);
#pragma unroll
                for (int nf = 0; nf < 4; nf++)
                    mma_f16(cacc[mf][nf], af, bh[nf]);
            }
        }
    };

    issue(0);
    issue(1);
    issue(2);
    for (int cc = 0; cc < NCH; cc++) {
        CP_WAIT(2);
        __syncthreads();
        if (cc + 3 < NCH) issue(cc + 3);
        else CP_COMMIT();
        compute(cc % CNSTG);
    }

    const int r0 = lane >> 2;
    const int cq = (lane & 3) * 2;
    float mul0[4], mul1[4], add0[4], add1[4];
#pragma unroll
    for (int nf = 0; nf < 4; nf++) {
        int n = n0 + wn * 32 + nf * 8 + cq;
        float b0 = __ldg(&bias[n]), b1 = __ldg(&bias[n + 1]);
        float s0 = __ldg(&bng[n]) * rsqrtf(__ldg(&bnv[n]) + 1e-3f);
        float s1 = __ldg(&bng[n + 1]) * rsqrtf(__ldg(&bnv[n + 1]) + 1e-3f);
        mul0[nf] = s0; mul1[nf] = s1;
        add0[nf] = s0 * (b0 - __ldg(&bnm[n])) + __ldg(&bnb[n]);
        add1[nf] = s1 * (b1 - __ldg(&bnm[n + 1])) + __ldg(&bnb[n + 1]);
    }
#pragma unroll
    for (int mf = 0; mf < 4; mf++) {
#pragma unroll
        for (int half = 0; half < 2; half++) {
            int m = wm * 64 + mf * 16 + r0 + half * 8;
#pragma unroll
            for (int nf = 0; nf < 4; nf++) {
                float v0 = fmaxf(fmaf(cacc[mf][nf][2 * half + 0], mul0[nf], add0[nf]), 0.f);
                float v1 = fmaxf(fmaf(cacc[mf][nf][2 * half + 1], mul1[nf], add1[nf]), 0.f);
                int nc = n0 + wn * 32 + nf * 8 + cq;
                size_t off = (size_t)bz * XPD_ + (size_t)(t0 + m + 2) * D_ + nc;
                *(uint32_t*)(Cp + off) = (uint32_t)f2h(v0) | ((uint32_t)f2h(v1) << 16);
            }
        }
    }
}

// ---------------- fused fw+bw LSTM-pre GEMM (1-term, colp-permuted out) ----------------
__global__ __launch_bounds__(256, 2) void mma_gemm_pre(
    const uint16_t* __restrict__ Ap,
    const uint16_t* __restrict__ Bhf, const uint16_t* __restrict__ Bhb,
    const float* __restrict__ bias_f, const float* __restrict__ bias_b,
    float* __restrict__ pre_f, float* __restrict__ pre_b)
{
    extern __shared__ char smraw[];
    const uint32_t sbase = smem_u32(smraw);
    const int KKtot = D_;

    const int tid = threadIdx.x;
    const int wid = tid >> 5, lane = tid & 31;
    const int bz = blockIdx.z;
    const int t0 = blockIdx.y * BM;
    const int fw = (blockIdx.x < 8);
    const int n0 = (blockIdx.x & 7) * BN;
    const int wm = wid & 1;
    const int wn = wid >> 1;

    const uint16_t* Bh = fw ? Bhf : Bhb;
    const float* bias = fw ? bias_f : bias_b;
    float* Cf = fw ? pre_f : pre_b;

    const uint32_t a_off = (uint32_t)((wm * 64 + (lane & 15)) * ROWB + (lane >> 4) * 16);
    const uint32_t b_off = (uint32_t)((wn * 32 + (lane & 7) + ((lane >> 4) << 3)) * ROWB
                                      + ((lane >> 3) & 1) * 16);

    const uint16_t* Ab = Ap + (size_t)bz * XPD_;
    const int NCH = KKtot / KC;

    float cacc[4][4][4];
#pragma unroll
    for (int i = 0; i < 4; i++)
#pragma unroll
        for (int j = 0; j < 4; j++)
#pragma unroll
            for (int q = 0; q < 4; q++) cacc[i][j][q] = 0.f;

    auto issue = [&](int cc) {
        const int st = cc % CNSTG;
        const int kk0 = cc * KC;
        const uint32_t sb = sbase + st * CSTAGEB;
#pragma unroll
        for (int half = 0; half < 2; half++) {
            const int s = tid + half * 256;
            const int row = s >> 2, seg = s & 3;
            const uint32_t doff = (uint32_t)(row * ROWB + seg * 16);
            const size_t aoff = (size_t)(t0 + row) * D_ + kk0 + seg * 8;
            const size_t boff = (size_t)(n0 + row) * KKtot + kk0 + seg * 8;
            CP16(sb + doff,         Ab + aoff);
            CP16(sb + TILEB + doff, Bh + boff);
        }
        CP_COMMIT();
    };

    auto compute = [&](int st) {
        const uint32_t SB = sbase + st * CSTAGEB;
#pragma unroll
        for (int k16 = 0; k16 < 2; k16++) {
            const uint32_t kof = k16 * 32;
            uint32_t bh[4][2];
#pragma unroll
            for (int nfp = 0; nfp < 2; nfp++) {
                uint32_t bd = SB + TILEB + b_off + nfp * (16 * ROWB) + kof;
                LDM_X4(bh[2 * nfp][0], bh[2 * nfp][1], bh[2 * nfp + 1][0], bh[2 * nfp + 1][1], bd);
            }
#pragma unroll
            for (int mf = 0; mf < 4; mf++) {
                uint32_t af[4];
                uint32_t ad = SB + a_off + mf * (16 * ROWB) + kof;
                LDM_X4(af[0], af[1], af[2], af[3], ad);
#pragma unroll
                for (int nf = 0; nf < 4; nf++)
                    mma_f16(cacc[mf][nf], af, bh[nf]);
            }
        }
    };

    issue(0);
    issue(1);
    issue(2);
    for (int cc = 0; cc < NCH; cc++) {
        CP_WAIT(2);
        __syncthreads();
        if (cc + 3 < NCH) issue(cc + 3);
        else CP_COMMIT();
        compute(cc % CNSTG);
    }

    const int r0 = lane >> 2;
    const int cq = (lane & 3) * 2;
    float add0[4], add1[4];
#pragma unroll
    for (int nf = 0; nf < 4; nf++) {
        int n = n0 + wn * 32 + nf * 8 + cq;
        add0[nf] = __ldg(&bias[n]);
        add1[nf] = __ldg(&bias[n + 1]);
    }
#pragma unroll
    for (int mf = 0; mf < 4; mf++) {
#pragma unroll
        for (int half = 0; half < 2; half++) {
            int m = wm * 64 + mf * 16 + r0 + half * 8;
            int t = t0 + m;
            size_t rowoff = fw ? ((size_t)t * B_ + bz) * G4_
                               : ((size_t)(T_ - 1 - t) * B_ + bz) * G4_;
#pragma unroll
            for (int nf = 0; nf < 4; nf++) {
                int nc = n0 + wn * 32 + nf * 8 + cq;
                int u = nc & 255, g = nc >> 8;
                float v0 = cacc[mf][nf][2 * half + 0] + add0[nf];
                float v1 = cacc[mf][nf][2 * half + 1] + add1[nf];
                Cf[rowoff + 4 * u + g] = v0;
                Cf[rowoff + 4 * (u + 1) + g] = v1;
            }
        }
    }
}

// ---------------- tensor-core bi-LSTM recurrence: h single fp16, W hi/lo ----------------
__global__ __launch_bounds__(256) void lstm_tc_kernel(
    const float* __restrict__ pre_f, const float* __restrict__ pre_b,
    float* __restrict__ out)
{
    extern __shared__ char smraw[];
    const uint32_t sbase = smem_u32(smraw);
    float* sOut = (float*)(smraw + LOUTOFF);

    const int bx = blockIdx.x;
    const int dir = bx >> 4;
    const int cta = bx & 15;
    const float* pre = dir ? pre_b : pre_f;
    unsigned* bar = &g_bar[dir];

    const int tid = threadIdx.x;
    const int wid = tid >> 5, lane = tid & 31;
    const int wm = wid & 1;
    const int wn = wid >> 1;
    const int gid = lane >> 2;
    const int lpair = lane & 3;
    const int isodd = lane & 1;

    // preload W hi/lo tiles (persistent)
    {
        const uint16_t* wh = g_wrh + (size_t)dir * 1024 * 256 + (size_t)cta * 64 * 256;
        const uint16_t* wl = g_wrl + (size_t)dir * 1024 * 256 + (size_t)cta * 64 * 256;
        for (int s = tid; s < 4096; s += 256) {
            int tile = s >> 8, row = (s >> 2) & 63, seg = s & 3;
            int p = tile & 1, c = tile >> 1;
            const uint16_t* src = (p ? wl : wh) + row * 256 + c * 32 + seg * 8;
            uint4 v = *(const uint4*)src;
            *(uint4*)(smraw + LWOFF + (c * 2 + p) * LTILE + row * ROWB + seg * 16) = v;
        }
    }

    const uint32_t a_off = (uint32_t)((wm * 32 + (lane & 15)) * ROWB + (lane >> 4) * 16);
    const uint32_t b_off = (uint32_t)(LWOFF + (wn * 16 + (lane & 7) + ((lane >> 4) << 3)) * ROWB
                                      + ((lane >> 3) & 1) * 16);

    float cst[2][2] = {{0.f, 0.f}, {0.f, 0.f}};
    __syncthreads();

    for (int t = 0; t < T_; t++) {
        float4 pv[2][2];
#pragma unroll
        for (int mf = 0; mf < 2; mf++)
#pragma unroll
            for (int n8 = 0; n8 < 2; n8++) {
                int b = wm * 32 + mf * 16 + gid + (isodd ? 8 : 0);
                int u = cta * 16 + wn * 4 + n8 * 2 + (lpair >> 1);
                pv[mf][n8] = __ldg((const float4*)(pre + ((size_t)t * B_ + b) * G4_ + 4 * u));
            }

        // stage h (hi only): 8 tiles, two half-groups of 4
        const int slot = (t + 1) & 1;
        const uint16_t* hhr = &g_hh[dir][slot][0];
#pragma unroll
        for (int half = 0; half < 2; half++) {
#pragma unroll
            for (int j = 0; j < 4; j++) {
                int s = tid + (half * 4 + j) * 256;
                int c = s >> 8, row = (s >> 2) & 63, seg = s & 3;
                const uint16_t* src = hhr + row * 256 + c * 32 + seg * 8;
                CP16(sbase + c * LTILE + (uint32_t)(row * ROWB + seg * 16), src);
            }
            CP_COMMIT();
        }

        float acc[2][2][4];
#pragma unroll
        for (int i = 0; i < 2; i++)
#pragma unroll
            for (int j = 0; j < 2; j++)
#pragma unroll
                for (int q = 0; q < 4; q++) acc[i][j][q] = 0.f;

        CP_WAIT(1);
        __syncthreads();
#pragma unroll
        for (int c = 0; c < 4; c++) {
#pragma unroll
            for (int k16 = 0; k16 < 2; k16++) {
                const uint32_t kof = k16 * 32;
                uint32_t bh[2][2], bl[2][2];
                LDM_X4(bh[0][0], bh[0][1], bh[1][0], bh[1][1],
                       b_off + (c * 2 + 0) * LTILE + kof + sbase);
                LDM_X4(bl[0][0], bl[0][1], bl[1][0], bl[1][1],
                       b_off + (c * 2 + 1) * LTILE + kof + sbase);
#pragma unroll
                for (int mf = 0; mf < 2; mf++) {
                    uint32_t ah[4];
                    LDM_X4(ah[0], ah[1], ah[2], ah[3],
                           sbase + c * LTILE + a_off + mf * (16 * ROWB) + kof);
#pragma unroll
                    for (int n8 = 0; n8 < 2; n8++) {
                        mma_f16(acc[mf][n8], ah, bh[n8]);
                        mma_f16(acc[mf][n8], ah, bl[n8]);
                    }
                }
            }
        }
        CP_WAIT(0);
        __syncthreads();
#pragma unroll
        for (int c = 4; c < 8; c++) {
#pragma unroll
            for (int k16 = 0; k16 < 2; k16++) {
                const uint32_t kof = k16 * 32;
                uint32_t bh[2][2], bl[2][2];
                LDM_X4(bh[0][0], bh[0][1], bh[1][0], bh[1][1],
                       b_off + (c * 2 + 0) * LTILE + kof + sbase);
                LDM_X4(bl[0][0], bl[0][1], bl[1][0], bl[1][1],
                       b_off + (c * 2 + 1) * LTILE + kof + sbase);
#pragma unroll
                for (int mf = 0; mf < 2; mf++) {
                    uint32_t ah[4];
                    LDM_X4(ah[0], ah[1], ah[2], ah[3],
                           sbase + c * LTILE + a_off + mf * (16 * ROWB) + kof);
#pragma unroll
                    for (int n8 = 0; n8 < 2; n8++) {
                        mma_f16(acc[mf][n8], ah, bh[n8]);
                        mma_f16(acc[mf][n8], ah, bl[n8]);
                    }
                }
            }
        }
        __syncthreads();

        uint16_t* hhw = &g_hh[dir][t & 1][0];
#pragma unroll
        for (int mf = 0; mf < 2; mf++) {
#pragma unroll
            for (int n8 = 0; n8 < 2; n8++) {
                float o0 = acc[mf][n8][0], o1 = acc[mf][n8][1];
                float o2 = acc[mf][n8][2], o3 = acc[mf][n8][3];
                float r0v = __shfl_xor_sync(0xFFFFFFFFu, o0, 1);
                float r1v = __shfl_xor_sync(0xFFFFFFFFu, o1, 1);
                float r2v = __shfl_xor_sync(0xFFFFFFFFu, o2, 1);
                float r3v = __shfl_xor_sync(0xFFFFFFFFu, o3, 1);
                float zi, zf, zg, zo;
                if (!isodd) { zi = o0;  zf = o1;  zg = r0v; zo = r1v; }
                else        { zi = r2v; zf = r3v; zg = o2;  zo = o3;  }
                float4 p4 = pv[mf][n8];
                zi += p4.x; zf += p4.y; zg += p4.z; zo += p4.w;
                float ig = 1.f / (1.f + __expf(-zi));
                float fg = 1.f / (1.f + __expf(-zf));
                float gg = tanhf(zg);
                float og = 1.f / (1.f + __expf(-zo));
                float cc = fg * cst[mf][n8] + ig * gg;
                cst[mf][n8] = cc;
                float h = og * tanhf(cc);

                int b = wm * 32 + mf * 16 + gid + (isodd ? 8 : 0);
                int u = cta * 16 + wn * 4 + n8 * 2 + (lpair >> 1);
                hhw[b * U_ + u] = f2h(h);
                sOut[b * 16 + (u & 15)] = h;
            }
        }

        __syncthreads();

        {
            int b = tid >> 2;
            int ul = (tid & 3) * 4;
            float4 hv = *(const float4*)(sOut + b * 16 + ul);
            int tout = dir ? (T_ - 1 - t) : t;
            *(float4*)(out + ((size_t)b * T_ + tout) * (2 * U_) + dir * U_ + cta * 16 + ul) = hv;
        }

        if (tid == 0) {
            __threadfence();
            atomicAdd(bar, 1u);
            unsigned target = (unsigned)(t + 1) * 16u;
            unsigned v;
            do {
                asm volatile("ld.global.acquire.gpu.u32 %0, [%1];" : "=r"(v) : "l"(bar));
            } while (v < target);
        }
        __syncthreads();
    }
}

// ---------------- launcher ----------------
extern "C" void kernel_launch(void* const* d_in, const int* in_sizes, int n_in,
                              void* d_out, int out_size)
{
    const float* inputs = (const float*)d_in[0];
    const float* convk  = (const float*)d_in[1];
    const float* convb  = (const float*)d_in[2];
    const float* bng    = (const float*)d_in[3];
    const float* bnb    = (const float*)d_in[4];
    const float* bnm    = (const float*)d_in[5];
    const float* bnv    = (const float*)d_in[6];
    const float* wk_f   = (const float*)d_in[7];
    const float* wr_f   = (const float*)d_in[8];
    const float* bi_f   = (const float*)d_in[9];
    const float* wk_b   = (const float*)d_in[10];
    const float* wr_b   = (const float*)d_in[11];
    const float* bi_b   = (const float*)d_in[12];
    float* out = (float*)d_out;

    uint16_t *x0, *x1, *wch, *wlh;
    float *pre_f, *pre_b;
    cudaGetSymbolAddress((void**)&x0, g_x0);
    cudaGetSymbolAddress((void**)&x1, g_x1);
    cudaGetSymbolAddress((void**)&wch, g_wch);
    cudaGetSymbolAddress((void**)&wlh, g_wlh);
    cudaGetSymbolAddress((void**)&pre_f, g_pre_f);
    cudaGetSymbolAddress((void**)&pre_b, g_pre_b);

    cudaFuncSetAttribute(mma_gemm_conv, cudaFuncAttributeMaxDynamicSharedMemorySize, CGSMEM);
    cudaFuncSetAttribute(mma_gemm_pre,  cudaFuncAttributeMaxDynamicSharedMemorySize, CGSMEM);
    cudaFuncSetAttribute(lstm_tc_kernel, cudaFuncAttributeMaxDynamicSharedMemorySize, LSMEM);

    prep_kernel<<<8192, 256>>>(inputs, convk, wk_f, wk_b, wr_f, wr_b);

    const size_t wcs = (size_t)512 * 2560;
    dim3 gc(D_ / BN, T_ / BM, B_);
    mma_gemm_conv<<<gc, 256, CGSMEM>>>(x0, wch + 0 * wcs,
                                       convb + 0 * D_, bng + 0 * D_, bnb + 0 * D_,
                                       bnm + 0 * D_, bnv + 0 * D_, x1);
    mma_gemm_conv<<<gc, 256, CGSMEM>>>(x1, wch + 1 * wcs,
                                       convb + 1 * D_, bng + 1 * D_, bnb + 1 * D_,
                                       bnm + 1 * D_, bnv + 1 * D_, x0);
    mma_gemm_conv<<<gc, 256, CGSMEM>>>(x0, wch + 2 * wcs,
                                       convb + 2 * D_, bng + 2 * D_, bnb + 2 * D_,
                                       bnm + 2 * D_, bnv + 2 * D_, x1);

    const size_t wls = (size_t)1024 * 512;
    dim3 gl(16, T_ / BM, B_);
    mma_gemm_pre<<<gl, 256, CGSMEM>>>(x1 + 2 * D_,
                                      wlh + 0 * wls, wlh + 1 * wls,
                                      bi_f, bi_b, pre_f, pre_b);

    lstm_tc_kernel<<<32, 256, LSMEM>>>(pre_f, pre_b, out);
}

// round 17
// speedup vs baseline: 2.0010x; 1.0487x over previous
#include <cuda_runtime.h>
#include <cuda_fp16.h>
#include <cstdint>
#include <math.h>

#define B_    64
#define T_    1024
#define D_    512
#define KTAP  5
#define U_    256
#define G4_   1024
#define TP_   (T_ + 4)
#define XPD_  (TP_ * D_)

#define BM    128
#define BN    128
#define KC    32
#define ROWB  80
#define TILEB (128 * ROWB)
#define CSTAGEB (2 * TILEB)          // A + Bh per stage
#define CNSTG 4
#define CGSMEM (CNSTG * CSTAGEB)     // 80 KB -> 2 CTAs/SM

// lstm tc kernel: 8 H tiles + 8 W tiles (hi only)
#define LTILE 5120
#define LWOFF (8 * LTILE)            // 40960
#define LOUTOFF (LWOFF + 8 * LTILE)  // 81920
#define LSMEM (LOUTOFF + 4096)       // 86016

// ---------------- scratch ----------------
__device__ uint16_t g_x0[(size_t)B_ * XPD_];
__device__ uint16_t g_x1[(size_t)B_ * XPD_];
__device__ uint16_t g_wch[(size_t)3 * 512 * 2560];  // conv weights fp16 [i][n][kk]
__device__ uint16_t g_wlh[(size_t)2 * 1024 * 512];  // lstm kernels fp16 [dir][n][d]
__device__ uint16_t g_wrh[(size_t)2 * 1024 * 256];  // recurrent W fp16 [dir][colp][k]
__device__ float    g_pre_f[(size_t)T_ * B_ * G4_]; // colp-permuted [t][b][4u+g]
__device__ float    g_pre_b[(size_t)T_ * B_ * G4_];
__device__ uint16_t g_hh[2][2][B_ * U_];            // h fp16 [dir][slot][b*256+u]
__device__ unsigned g_bar[2];

// ---------------- helpers ----------------
__device__ __forceinline__ uint32_t smem_u32(const void* p) {
    uint32_t a;
    asm("{ .reg .u64 t; cvta.to.shared.u64 t, %1; cvt.u32.u64 %0, t; }" : "=r"(a) : "l"(p));
    return a;
}
__device__ __forceinline__ uint16_t f2h(float v) {
    return __half_as_ushort(__float2half(v));
}
#define CP16(dst, src) \
    asm volatile("cp.async.cg.shared.global [%0], [%1], 16;" :: "r"(dst), "l"(src))
#define CP_COMMIT() asm volatile("cp.async.commit_group;" ::: "memory")
#define CP_WAIT(N)  asm volatile("cp.async.wait_group %0;" :: "n"(N) : "memory")
#define LDM_X4(R0, R1, R2, R3, ADDR)                                            \
    asm volatile("ldmatrix.sync.aligned.m8n8.x4.shared.b16 {%0,%1,%2,%3}, [%4];"\
        : "=r"(R0), "=r"(R1), "=r"(R2), "=r"(R3) : "r"(ADDR))
__device__ __forceinline__ void mma_f16(float* c, const uint32_t* a, const uint32_t* b) {
    asm volatile(
        "mma.sync.aligned.m16n8k16.row.col.f32.f16.f16.f32 "
        "{%0,%1,%2,%3}, {%4,%5,%6,%7}, {%8,%9}, {%0,%1,%2,%3};"
        : "+f"(c[0]), "+f"(c[1]), "+f"(c[2]), "+f"(c[3])
        : "r"(a[0]), "r"(a[1]), "r"(a[2]), "r"(a[3]), "r"(b[0]), "r"(b[1]));
}

// ---------------- fused prep ----------------
__global__ void prep_kernel(const float* __restrict__ in,
                            const float* __restrict__ convk,
                            const float* __restrict__ wkf,
                            const float* __restrict__ wkb,
                            const float* __restrict__ wrf,
                            const float* __restrict__ wrb) {
    const size_t stride = (size_t)gridDim.x * blockDim.x;
    const size_t tid0 = (size_t)blockIdx.x * blockDim.x + threadIdx.x;

    for (size_t idx = tid0; idx < (size_t)B_ * 4 * D_; idx += stride) {
        int b = (int)(idx / (4 * D_));
        int r = (int)((idx / D_) & 3);
        int d = (int)(idx % D_);
        int row = (r < 2) ? r : (TP_ - 4 + r);
        size_t o = (size_t)b * XPD_ + (size_t)row * D_ + d;
        g_x0[o] = 0; g_x1[o] = 0;
    }
    for (size_t idx = tid0; idx < (size_t)2 * 2 * B_ * U_ / 2; idx += stride)
        ((uint32_t*)g_hh)[idx] = 0u;
    if (tid0 < 2) g_bar[tid0] = 0u;

    for (size_t idx = tid0; idx < (size_t)B_ * T_ * D_; idx += stride) {
        size_t b = idx / ((size_t)T_ * D_);
        size_t r = idx % ((size_t)T_ * D_);
        size_t t = r / D_, d = r % D_;
        g_x0[b * XPD_ + (t + 2) * D_ + d] = f2h(in[idx]);
    }

    const size_t CONVN = (size_t)3 * 512 * 2560;
    const size_t LSTMN = (size_t)1024 * 512;
    for (size_t idx = tid0; idx < CONVN + 2 * LSTMN; idx += stride) {
        if (idx < CONVN) {
            size_t i = idx / ((size_t)512 * 2560);
            size_t r = idx % ((size_t)512 * 2560);
            size_t n = r / 2560, kk = r % 2560;
            size_t tap = kk >> 9, din = kk & 511;
            g_wch[idx] = f2h(convk[(((i * KTAP + tap) * D_) + din) * D_ + n]);
        } else if (idx < CONVN + LSTMN) {
            size_t j = idx - CONVN;
            size_t n = j >> 9, d = j & 511;
            g_wlh[j] = f2h(wkf[d * G4_ + n]);
        } else {
            size_t j = idx - CONVN - LSTMN;
            size_t n = j >> 9, d = j & 511;
            g_wlh[LSTMN + j] = f2h(wkb[d * G4_ + n]);
        }
    }

    const size_t WRN = (size_t)2 * 1024 * 256;
    for (size_t idx = tid0; idx < WRN; idx += stride) {
        size_t dir = idx >> 18;
        size_t r = idx & 262143;
        size_t colp = r >> 8, k = r & 255;
        size_t u = colp >> 2, g = colp & 3;
        const float* wr = dir ? wrb : wrf;
        g_wrh[idx] = f2h(wr[k * G4_ + g * U_ + u]);
    }
}

// ---------------- fp16 1-term warp-MMA conv GEMM, 4-stage pipeline ----------------
__global__ __launch_bounds__(256, 2) void mma_gemm_conv(
    const uint16_t* __restrict__ Ap,
    const uint16_t* __restrict__ Bh,
    const float* __restrict__ bias,
    const float* __restrict__ bng, const float* __restrict__ bnb,
    const float* __restrict__ bnm, const float* __restrict__ bnv,
    uint16_t* __restrict__ Cp)
{
    extern __shared__ char smraw[];
    const uint32_t sbase = smem_u32(smraw);
    const int KKtot = KTAP * D_;

    const int tid = threadIdx.x;
    const int wid = tid >> 5, lane = tid & 31;
    const int bz = blockIdx.z;
    const int t0 = blockIdx.y * BM;
    const int n0 = blockIdx.x * BN;
    const int wm = wid & 1;
    const int wn = wid >> 1;

    const uint32_t a_off = (uint32_t)((wm * 64 + (lane & 15)) * ROWB + (lane >> 4) * 16);
    const uint32_t b_off = (uint32_t)((wn * 32 + (lane & 7) + ((lane >> 4) << 3)) * ROWB
                                      + ((lane >> 3) & 1) * 16);

    const uint16_t* Ab = Ap + (size_t)bz * XPD_;
    const int NCH = KKtot / KC;

    float cacc[4][4][4];
#pragma unroll
    for (int i = 0; i < 4; i++)
#pragma unroll
        for (int j = 0; j < 4; j++)
#pragma unroll
            for (int q = 0; q < 4; q++) cacc[i][j][q] = 0.f;

    auto issue = [&](int cc) {
        const int st = cc % CNSTG;
        const int kk0 = cc * KC;
        const int tap = kk0 >> 9;
        const int d0 = kk0 & 511;
        const uint32_t sb = sbase + st * CSTAGEB;
#pragma unroll
        for (int half = 0; half < 2; half++) {
            const int s = tid + half * 256;
            const int row = s >> 2, seg = s & 3;
            const uint32_t doff = (uint32_t)(row * ROWB + seg * 16);
            const size_t aoff = (size_t)(t0 + row + tap) * D_ + d0 + seg * 8;
            const size_t boff = (size_t)(n0 + row) * KKtot + kk0 + seg * 8;
            CP16(sb + doff,         Ab + aoff);
            CP16(sb + TILEB + doff, Bh + boff);
        }
        CP_COMMIT();
    };

    auto compute = [&](int st) {
        const uint32_t SB = sbase + st * CSTAGEB;
#pragma unroll
        for (int k16 = 0; k16 < 2; k16++) {
            const uint32_t kof = k16 * 32;
            uint32_t bh[4][2];
#pragma unroll
            for (int nfp = 0; nfp < 2; nfp++) {
                uint32_t bd = SB + TILEB + b_off + nfp * (16 * ROWB) + kof;
                LDM_X4(bh[2 * nfp][0], bh[2 * nfp][1], bh[2 * nfp + 1][0], bh[2 * nfp + 1][1], bd);
            }
#pragma unroll
            for (int mf = 0; mf < 4; mf++) {
                uint32_t af[4];
                uint32_t ad = SB + a_off + mf * (16 * ROWB) + kof;
                LDM_X4(af[0], af[1], af[2], af[3], ad);
#pragma unroll
                for (int nf = 0; nf < 4; nf++)
                    mma_f16(cacc[mf][nf], af, bh[nf]);
            }
        }
    };

    issue(0);
    issue(1);
    issue(2);
    for (int cc = 0; cc < NCH; cc++) {
        CP_WAIT(2);
        __syncthreads();
        if (cc + 3 < NCH) issue(cc + 3);
        else CP_COMMIT();
        compute(cc % CNSTG);
    }

    const int r0 = lane >> 2;
    const int cq = (lane & 3) * 2;
    float mul0[4], mul1[4], add0[4], add1[4];
#pragma unroll
    for (int nf = 0; nf < 4; nf++) {
        int n = n0 + wn * 32 + nf * 8 + cq;
        float b0 = __ldg(&bias[n]), b1 = __ldg(&bias[n + 1]);
        float s0 = __ldg(&bng[n]) * rsqrtf(__ldg(&bnv[n]) + 1e-3f);
        float s1 = __ldg(&bng[n + 1]) * rsqrtf(__ldg(&bnv[n + 1]) + 1e-3f);
        mul0[nf] = s0; mul1[nf] = s1;
        add0[nf] = s0 * (b0 - __ldg(&bnm[n])) + __ldg(&bnb[n]);
        add1[nf] = s1 * (b1 - __ldg(&bnm[n + 1])) + __ldg(&bnb[n + 1]);
    }
#pragma unroll
    for (int mf = 0; mf < 4; mf++) {
#pragma unroll
        for (int half = 0; half < 2; half++) {
            int m = wm * 64 + mf * 16 + r0 + half * 8;
#pragma unroll
            for (int nf = 0; nf < 4; nf++) {
                float v0 = fmaxf(fmaf(cacc[mf][nf][2 * half + 0], mul0[nf], add0[nf]), 0.f);
                float v1 = fmaxf(fmaf(cacc[mf][nf][2 * half + 1], mul1[nf], add1[nf]), 0.f);
                int nc = n0 + wn * 32 + nf * 8 + cq;
                size_t off = (size_t)bz * XPD_ + (size_t)(t0 + m + 2) * D_ + nc;
                *(uint32_t*)(Cp + off) = (uint32_t)f2h(v0) | ((uint32_t)f2h(v1) << 16);
            }
        }
    }
}

// ---------------- fused fw+bw LSTM-pre GEMM (1-term, colp-permuted out) ----------------
__global__ __launch_bounds__(256, 2) void mma_gemm_pre(
    const uint16_t* __restrict__ Ap,
    const uint16_t* __restrict__ Bhf, const uint16_t* __restrict__ Bhb,
    const float* __restrict__ bias_f, const float* __restrict__ bias_b,
    float* __restrict__ pre_f, float* __restrict__ pre_b)
{
    extern __shared__ char smraw[];
    const uint32_t sbase = smem_u32(smraw);
    const int KKtot = D_;

    const int tid = threadIdx.x;
    const int wid = tid >> 5, lane = tid & 31;
    const int bz = blockIdx.z;
    const int t0 = blockIdx.y * BM;
    const int fw = (blockIdx.x < 8);
    const int n0 = (blockIdx.x & 7) * BN;
    const int wm = wid & 1;
    const int wn = wid >> 1;

    const uint16_t* Bh = fw ? Bhf : Bhb;
    const float* bias = fw ? bias_f : bias_b;
    float* Cf = fw ? pre_f : pre_b;

    const uint32_t a_off = (uint32_t)((wm * 64 + (lane & 15)) * ROWB + (lane >> 4) * 16);
    const uint32_t b_off = (uint32_t)((wn * 32 + (lane & 7) + ((lane >> 4) << 3)) * ROWB
                                      + ((lane >> 3) & 1) * 16);

    const uint16_t* Ab = Ap + (size_t)bz * XPD_;
    const int NCH = KKtot / KC;

    float cacc[4][4][4];
#pragma unroll
    for (int i = 0; i < 4; i++)
#pragma unroll
        for (int j = 0; j < 4; j++)
#pragma unroll
            for (int q = 0; q < 4; q++) cacc[i][j][q] = 0.f;

    auto issue = [&](int cc) {
        const int st = cc % CNSTG;
        const int kk0 = cc * KC;
        const uint32_t sb = sbase + st * CSTAGEB;
#pragma unroll
        for (int half = 0; half < 2; half++) {
            const int s = tid + half * 256;
            const int row = s >> 2, seg = s & 3;
            const uint32_t doff = (uint32_t)(row * ROWB + seg * 16);
            const size_t aoff = (size_t)(t0 + row) * D_ + kk0 + seg * 8;
            const size_t boff = (size_t)(n0 + row) * KKtot + kk0 + seg * 8;
            CP16(sb + doff,         Ab + aoff);
            CP16(sb + TILEB + doff, Bh + boff);
        }
        CP_COMMIT();
    };

    auto compute = [&](int st) {
        const uint32_t SB = sbase + st * CSTAGEB;
#pragma unroll
        for (int k16 = 0; k16 < 2; k16++) {
            const uint32_t kof = k16 * 32;
            uint32_t bh[4][2];
#pragma unroll
            for (int nfp = 0; nfp < 2; nfp++) {
                uint32_t bd = SB + TILEB + b_off + nfp * (16 * ROWB) + kof;
                LDM_X4(bh[2 * nfp][0], bh[2 * nfp][1], bh[2 * nfp + 1][0], bh[2 * nfp + 1][1], bd);
            }
#pragma unroll
            for (int mf = 0; mf < 4; mf++) {
                uint32_t af[4];
                uint32_t ad = SB + a_off + mf * (16 * ROWB) + kof;
                LDM_X4(af[0], af[1], af[2], af[3], ad);
#pragma unroll
                for (int nf = 0; nf < 4; nf++)
                    mma_f16(cacc[mf][nf], af, bh[nf]);
            }
        }
    };

    issue(0);
    issue(1);
    issue(2);
    for (int cc = 0; cc < NCH; cc++) {
        CP_WAIT(2);
        __syncthreads();
        if (cc + 3 < NCH) issue(cc + 3);
        else CP_COMMIT();
        compute(cc % CNSTG);
    }

    const int r0 = lane >> 2;
    const int cq = (lane & 3) * 2;
    float add0[4], add1[4];
#pragma unroll
    for (int nf = 0; nf < 4; nf++) {
        int n = n0 + wn * 32 + nf * 8 + cq;
        add0[nf] = __ldg(&bias[n]);
        add1[nf] = __ldg(&bias[n + 1]);
    }
#pragma unroll
    for (int mf = 0; mf < 4; mf++) {
#pragma unroll
        for (int half = 0; half < 2; half++) {
            int m = wm * 64 + mf * 16 + r0 + half * 8;
            int t = t0 + m;
            size_t rowoff = fw ? ((size_t)t * B_ + bz) * G4_
                               : ((size_t)(T_ - 1 - t) * B_ + bz) * G4_;
#pragma unroll
            for (int nf = 0; nf < 4; nf++) {
                int nc = n0 + wn * 32 + nf * 8 + cq;
                int u = nc & 255, g = nc >> 8;
                float v0 = cacc[mf][nf][2 * half + 0] + add0[nf];
                float v1 = cacc[mf][nf][2 * half + 1] + add1[nf];
                Cf[rowoff + 4 * u + g] = v0;
                Cf[rowoff + 4 * (u + 1) + g] = v1;
            }
        }
    }
}

// ---------------- tensor-core bi-LSTM recurrence: single-term fp16 ----------------
__global__ __launch_bounds__(256) void lstm_tc_kernel(
    const float* __restrict__ pre_f, const float* __restrict__ pre_b,
    float* __restrict__ out)
{
    extern __shared__ char smraw[];
    const uint32_t sbase = smem_u32(smraw);
    float* sOut = (float*)(smraw + LOUTOFF);

    const int bx = blockIdx.x;
    const int dir = bx >> 4;
    const int cta = bx & 15;
    const float* pre = dir ? pre_b : pre_f;
    unsigned* bar = &g_bar[dir];

    const int tid = threadIdx.x;
    const int wid = tid >> 5, lane = tid & 31;
    const int wm = wid & 1;
    const int wn = wid >> 1;
    const int gid = lane >> 2;
    const int lpair = lane & 3;
    const int isodd = lane & 1;

    // preload W tiles (hi only, 8 tiles, persistent)
    {
        const uint16_t* wh = g_wrh + (size_t)dir * 1024 * 256 + (size_t)cta * 64 * 256;
        for (int s = tid; s < 2048; s += 256) {
            int c = s >> 8, row = (s >> 2) & 63, seg = s & 3;
            const uint16_t* src = wh + row * 256 + c * 32 + seg * 8;
            uint4 v = *(const uint4*)src;
            *(uint4*)(smraw + LWOFF + c * LTILE + row * ROWB + seg * 16) = v;
        }
    }

    const uint32_t a_off = (uint32_t)((wm * 32 + (lane & 15)) * ROWB + (lane >> 4) * 16);
    const uint32_t b_off = (uint32_t)(LWOFF + (wn * 16 + (lane & 7) + ((lane >> 4) << 3)) * ROWB
                                      + ((lane >> 3) & 1) * 16);

    float cst[2][2] = {{0.f, 0.f}, {0.f, 0.f}};
    __syncthreads();

    for (int t = 0; t < T_; t++) {
        float4 pv[2][2];
#pragma unroll
        for (int mf = 0; mf < 2; mf++)
#pragma unroll
            for (int n8 = 0; n8 < 2; n8++) {
                int b = wm * 32 + mf * 16 + gid + (isodd ? 8 : 0);
                int u = cta * 16 + wn * 4 + n8 * 2 + (lpair >> 1);
                pv[mf][n8] = __ldg((const float4*)(pre + ((size_t)t * B_ + b) * G4_ + 4 * u));
            }

        // stage h (hi only): 8 tiles, two half-groups of 4
        const int slot = (t + 1) & 1;
        const uint16_t* hhr = &g_hh[dir][slot][0];
#pragma unroll
        for (int half = 0; half < 2; half++) {
#pragma unroll
            for (int j = 0; j < 4; j++) {
                int s = tid + (half * 4 + j) * 256;
                int c = s >> 8, row = (s >> 2) & 63, seg = s & 3;
                const uint16_t* src = hhr + row * 256 + c * 32 + seg * 8;
                CP16(sbase + c * LTILE + (uint32_t)(row * ROWB + seg * 16), src);
            }
            CP_COMMIT();
        }

        float acc[2][2][4];
#pragma unroll
        for (int i = 0; i < 2; i++)
#pragma unroll
            for (int j = 0; j < 2; j++)
#pragma unroll
                for (int q = 0; q < 4; q++) acc[i][j][q] = 0.f;

        CP_WAIT(1);
        __syncthreads();
#pragma unroll
        for (int c = 0; c < 4; c++) {
#pragma unroll
            for (int k16 = 0; k16 < 2; k16++) {
                const uint32_t kof = k16 * 32;
                uint32_t bh[2][2];
                LDM_X4(bh[0][0], bh[0][1], bh[1][0], bh[1][1],
                       sbase + b_off + c * LTILE + kof);
#pragma unroll
                for (int mf = 0; mf < 2; mf++) {
                    uint32_t ah[4];
                    LDM_X4(ah[0], ah[1], ah[2], ah[3],
                           sbase + c * LTILE + a_off + mf * (16 * ROWB) + kof);
#pragma unroll
                    for (int n8 = 0; n8 < 2; n8++)
                        mma_f16(acc[mf][n8], ah, bh[n8]);
                }
            }
        }
        CP_WAIT(0);
        __syncthreads();
#pragma unroll
        for (int c = 4; c < 8; c++) {
#pragma unroll
            for (int k16 = 0; k16 < 2; k16++) {
                const uint32_t kof = k16 * 32;
                uint32_t bh[2][2];
                LDM_X4(bh[0][0], bh[0][1], bh[1][0], bh[1][1],
                       sbase + b_off + c * LTILE + kof);
#pragma unroll
                for (int mf = 0; mf < 2; mf++) {
                    uint32_t ah[4];
                    LDM_X4(ah[0], ah[1], ah[2], ah[3],
                           sbase + c * LTILE + a_off + mf * (16 * ROWB) + kof);
#pragma unroll
                    for (int n8 = 0; n8 < 2; n8++)
                        mma_f16(acc[mf][n8], ah, bh[n8]);
                }
            }
        }
        __syncthreads();

        uint16_t* hhw = &g_hh[dir][t & 1][0];
#pragma unroll
        for (int mf = 0; mf < 2; mf++) {
#pragma unroll
            for (int n8 = 0; n8 < 2; n8++) {
                float o0 = acc[mf][n8][0], o1 = acc[mf][n8][1];
                float o2 = acc[mf][n8][2], o3 = acc[mf][n8][3];
                float r0v = __shfl_xor_sync(0xFFFFFFFFu, o0, 1);
                float r1v = __shfl_xor_sync(0xFFFFFFFFu, o1, 1);
                float r2v = __shfl_xor_sync(0xFFFFFFFFu, o2, 1);
                float r3v = __shfl_xor_sync(0xFFFFFFFFu, o3, 1);
                float zi, zf, zg, zo;
                if (!isodd) { zi = o0;  zf = o1;  zg = r0v; zo = r1v; }
                else        { zi = r2v; zf = r3v; zg = o2;  zo = o3;  }
                float4 p4 = pv[mf][n8];
                zi += p4.x; zf += p4.y; zg += p4.z; zo += p4.w;
                float ig = 1.f / (1.f + __expf(-zi));
                float fg = 1.f / (1.f + __expf(-zf));
                float gg = tanhf(zg);
                float og = 1.f / (1.f + __expf(-zo));
                float cc = fg * cst[mf][n8] + ig * gg;
                cst[mf][n8] = cc;
                float h = og * tanhf(cc);

                int b = wm * 32 + mf * 16 + gid + (isodd ? 8 : 0);
                int u = cta * 16 + wn * 4 + n8 * 2 + (lpair >> 1);
                hhw[b * U_ + u] = f2h(h);
                sOut[b * 16 + (u & 15)] = h;
            }
        }

        __syncthreads();

        {
            int b = tid >> 2;
            int ul = (tid & 3) * 4;
            float4 hv = *(const float4*)(sOut + b * 16 + ul);
            int tout = dir ? (T_ - 1 - t) : t;
            *(float4*)(out + ((size_t)b * T_ + tout) * (2 * U_) + dir * U_ + cta * 16 + ul) = hv;
        }

        if (tid == 0) {
            __threadfence();
            atomicAdd(bar, 1u);
            unsigned target = (unsigned)(t + 1) * 16u;
            unsigned v;
            do {
                asm volatile("ld.global.acquire.gpu.u32 %0, [%1];" : "=r"(v) : "l"(bar));
            } while (v < target);
        }
        __syncthreads();
    }
}

// ---------------- launcher ----------------
extern "C" void kernel_launch(void* const* d_in, const int* in_sizes, int n_in,
                              void* d_out, int out_size)
{
    const float* inputs = (const float*)d_in[0];
    const float* convk  = (const float*)d_in[1];
    const float* convb  = (const float*)d_in[2];
    const float* bng    = (const float*)d_in[3];
    const float* bnb    = (const float*)d_in[4];
    const float* bnm    = (const float*)d_in[5];
    const float* bnv    = (const float*)d_in[6];
    const float* wk_f   = (const float*)d_in[7];
    const float* wr_f   = (const float*)d_in[8];
    const float* bi_f   = (const float*)d_in[9];
    const float* wk_b   = (const float*)d_in[10];
    const float* wr_b   = (const float*)d_in[11];
    const float* bi_b   = (const float*)d_in[12];
    float* out = (float*)d_out;

    uint16_t *x0, *x1, *wch, *wlh;
    float *pre_f, *pre_b;
    cudaGetSymbolAddress((void**)&x0, g_x0);
    cudaGetSymbolAddress((void**)&x1, g_x1);
    cudaGetSymbolAddress((void**)&wch, g_wch);
    cudaGetSymbolAddress((void**)&wlh, g_wlh);
    cudaGetSymbolAddress((void**)&pre_f, g_pre_f);
    cudaGetSymbolAddress((void**)&pre_b, g_pre_b);

    cudaFuncSetAttribute(mma_gemm_conv, cudaFuncAttributeMaxDynamicSharedMemorySize, CGSMEM);
    cudaFuncSetAttribute(mma_gemm_pre,  cudaFuncAttributeMaxDynamicSharedMemorySize, CGSMEM);
    cudaFuncSetAttribute(lstm_tc_kernel, cudaFuncAttributeMaxDynamicSharedMemorySize, LSMEM);

    prep_kernel<<<8192, 256>>>(inputs, convk, wk_f, wk_b, wr_f, wr_b);

    const size_t wcs = (size_t)512 * 2560;
    dim3 gc(D_ / BN, T_ / BM, B_);
    mma_gemm_conv<<<gc, 256, CGSMEM>>>(x0, wch + 0 * wcs,
                                       convb + 0 * D_, bng + 0 * D_, bnb + 0 * D_,
                                       bnm + 0 * D_, bnv + 0 * D_, x1);
    mma_gemm_conv<<<gc, 256, CGSMEM>>>(x1, wch + 1 * wcs,
                                       convb + 1 * D_, bng + 1 * D_, bnb + 1 * D_,
                                       bnm + 1 * D_, bnv + 1 * D_, x0);
    mma_gemm_conv<<<gc, 256, CGSMEM>>>(x0, wch + 2 * wcs,
                                       convb + 2 * D_, bng + 2 * D_, bnb + 2 * D_,
                                       bnm + 2 * D_, bnv + 2 * D_, x1);

    const size_t wls = (size_t)1024 * 512;
    dim3 gl(16, T_ / BM, B_);
    mma_gemm_pre<<<gl, 256, CGSMEM>>>(x1 + 2 * D_,
                                      wlh + 0 * wls, wlh + 1 * wls,
                                      bi_f, bi_b, pre_f, pre_b);

    lstm_tc_kernel<<<32, 256, LSMEM>>>(pre_f, pre_b, out);
}